// round 1
// baseline (speedup 1.0000x reference)
#include <cuda_runtime.h>
#include <math.h>

#define NN 524288
#define EE 4194304
#define BB 16384
#define COMBW 432
#define SLOPE 0.2f

// ---------------- scratch (device globals; no allocation allowed) ----------------
__device__ int   d_rowptr[NN + 1];
__device__ int   d_cursor[NN];
__device__ int   d_bsum[512];
__device__ int   d_col[EE + NN];
__device__ float d_hbuf[NN * 32];
__device__ float d_gbuf[NN * 32];
__device__ float d_sv[NN];
__device__ float d_tvv[NN];
__device__ float d_fp1[BB * 400];
__device__ float d_tv1[BB * 400];
__device__ float d_comb[BB * COMBW];
__device__ float d_c1[BB * 100];
__device__ float d_scl[1300];
__device__ float d_shf[1300];

// ---------------- CSR build ----------------
__global__ void k_init_deg() {
    int i = blockIdx.x * blockDim.x + threadIdx.x;
    if (i < NN) d_cursor[i] = 1;   // self-loop contributes 1
}

__global__ void k_count(const int* __restrict__ ei, int E) {
    int e = blockIdx.x * blockDim.x + threadIdx.x;
    if (e >= E) return;
    atomicAdd(&d_cursor[ei[E + e]], 1);   // dst row
}

__global__ void k_blocksum() {            // 512 blocks x 1024 threads
    __shared__ int s[1024];
    int i = blockIdx.x * 1024 + threadIdx.x;
    s[threadIdx.x] = d_cursor[i];
    __syncthreads();
    for (int o = 512; o > 0; o >>= 1) {
        if (threadIdx.x < o) s[threadIdx.x] += s[threadIdx.x + o];
        __syncthreads();
    }
    if (threadIdx.x == 0) d_bsum[blockIdx.x] = s[0];
}

__global__ void k_scan_bsums() {          // 1 block x 512 threads
    __shared__ int s[512];
    int tid = threadIdx.x;
    int v = d_bsum[tid];
    s[tid] = v;
    __syncthreads();
    for (int o = 1; o < 512; o <<= 1) {
        int t = (tid >= o) ? s[tid - o] : 0;
        __syncthreads();
        s[tid] += t;
        __syncthreads();
    }
    d_bsum[tid] = s[tid] - v;  // exclusive
}

__global__ void k_scan_final() {          // 512 blocks x 1024 threads
    __shared__ int s[1024];
    int tid = threadIdx.x;
    int i = blockIdx.x * 1024 + tid;
    int v = d_cursor[i];
    s[tid] = v;
    __syncthreads();
    for (int o = 1; o < 1024; o <<= 1) {
        int t = (tid >= o) ? s[tid - o] : 0;
        __syncthreads();
        s[tid] += t;
        __syncthreads();
    }
    int ex = s[tid] - v + d_bsum[blockIdx.x];
    d_rowptr[i] = ex;
    d_cursor[i] = ex;
    if (i == NN - 1) d_rowptr[NN] = ex + v;
}

__global__ void k_fill(const int* __restrict__ ei, int E) {
    int e = blockIdx.x * blockDim.x + threadIdx.x;
    if (e >= E + NN) return;
    int src, dst;
    if (e < E) { src = ei[e]; dst = ei[E + e]; }
    else       { src = dst = e - E; }
    int pos = atomicAdd(&d_cursor[dst], 1);
    d_col[pos] = src;
}

// ---------------- node-wise linear: h = X@W, s = h@a_src, t = h@a_dst ----------------
template <int CIN, int CINS, int COUT, int COUTS>
__global__ void k_node_linear(const float* __restrict__ X, const float* __restrict__ W,
                              const float* __restrict__ asrc, const float* __restrict__ adst,
                              float* __restrict__ H, float* __restrict__ S, float* __restrict__ T) {
    __shared__ float sW[CIN * COUT];
    __shared__ float sa[COUT], sd[COUT];
    for (int i = threadIdx.x; i < CIN * COUT; i += blockDim.x) sW[i] = W[i];
    for (int i = threadIdx.x; i < COUT; i += blockDim.x) { sa[i] = asrc[i]; sd[i] = adst[i]; }
    __syncthreads();
    int i = blockIdx.x * blockDim.x + threadIdx.x;
    if (i >= NN) return;
    float xr[CIN];
#pragma unroll
    for (int k = 0; k < CIN; k++) xr[k] = X[(long)i * CINS + k];
    float acc[COUT];
#pragma unroll
    for (int j = 0; j < COUT; j++) acc[j] = 0.f;
#pragma unroll
    for (int k = 0; k < CIN; k++) {
        float xv = xr[k];
#pragma unroll
        for (int j = 0; j < COUT; j++) acc[j] = fmaf(xv, sW[k * COUT + j], acc[j]);
    }
    float s = 0.f, t = 0.f;
#pragma unroll
    for (int j = 0; j < COUT; j++) { s = fmaf(acc[j], sa[j], s); t = fmaf(acc[j], sd[j], t); }
#pragma unroll
    for (int j = 0; j < COUTS; j++)
        H[(long)i * COUTS + j] = (j < COUT) ? acc[j] : 0.f;
    S[i] = s;
    T[i] = t;
}

// ---------------- GAT aggregation: warp per dst, lane per feature, online softmax ----------------
template <int C, int HS, int OUTS>
__global__ void k_gat_agg(const float* __restrict__ H, const float* __restrict__ S,
                          const float* __restrict__ T, const float* __restrict__ bias,
                          float* __restrict__ OUT) {
    int warp = (blockIdx.x * blockDim.x + threadIdx.x) >> 5;
    int lane = threadIdx.x & 31;
    if (warp >= NN) return;
    int p0 = d_rowptr[warp];
    int p1 = d_rowptr[warp + 1];
    float ti = T[warp];
    float m = -INFINITY, sum = 0.f, acc = 0.f;
    for (int p = p0; p < p1; p++) {
        int src = __ldg(&d_col[p]);
        float e = S[src] + ti;
        e = (e > 0.f) ? e : SLOPE * e;
        float hv = (lane < C) ? H[(long)src * HS + lane] : 0.f;
        if (e > m) {
            float sc = __expf(m - e);   // m = -inf first iter -> 0
            sum = sum * sc + 1.f;
            acc = acc * sc + hv;
            m = e;
        } else {
            float w = __expf(e - m);
            sum += w;
            acc = fmaf(w, hv, acc);
        }
    }
    if (lane < C) {
        float v = acc / sum + bias[lane];
        OUT[(long)warp * OUTS + lane] = (v > 0.f) ? v : 0.f;
    } else if (lane < OUTS) {
        OUT[(long)warp * OUTS + lane] = 0.f;
    }
}

// ---------------- pool: warp per graph (batch is sorted), lane per feature ----------------
__global__ void k_pool(const int* __restrict__ batch, const float* __restrict__ G,
                       float* __restrict__ comb) {
    int warp = (blockIdx.x * blockDim.x + threadIdx.x) >> 5;
    int lane = threadIdx.x & 31;
    if (warp >= BB) return;
    int b = warp;
    int lo = 0, hi = NN;
    while (lo < hi) { int mid = (lo + hi) >> 1; if (batch[mid] < b) lo = mid + 1; else hi = mid; }
    int start = lo;
    hi = NN;
    while (lo < hi) { int mid = (lo + hi) >> 1; if (batch[mid] < b + 1) lo = mid + 1; else hi = mid; }
    int end = lo;
    float s = 0.f;
    for (int r = start; r < end; r++) s += G[(long)r * 32 + lane];
    comb[(long)b * COMBW + lane] = s;
}

// ---------------- epilogue prep: fold bias + BN into scale/shift ----------------
__global__ void k_prep(const float* __restrict__ bias, const float* __restrict__ bn, int n,
                       float* __restrict__ sc, float* __restrict__ sh) {
    int j = blockIdx.x * blockDim.x + threadIdx.x;
    if (j >= n) return;
    float g = bn[j], be = bn[n + j], mu = bn[2 * n + j], va = bn[3 * n + j];
    float s = g * rsqrtf(va + 1e-5f);
    sc[j] = s;
    sh[j] = (bias[j] - mu) * s + be;
}

// ---------------- SGEMM (fp32) with fused scale/shift + ReLU epilogue ----------------
// C[m*ldc + cofs + n] = relu( (A[M,K] @ B[K,N])[m,n] * sc[n] + sh[n] )
__global__ __launch_bounds__(256) void k_sgemm(
    const float* __restrict__ A, const float* __restrict__ Bw,
    float* __restrict__ C, int M, int N, int K, int ldc, int cofs,
    const float* __restrict__ sc, const float* __restrict__ sh) {
    const int BM = 128, BN = 64, BK = 16;
    __shared__ float As[BK][BM];
    __shared__ float Bs[BK][BN];
    int tid = threadIdx.x;
    int bm = blockIdx.y * BM;
    int bn = blockIdx.x * BN;
    int ty = tid >> 4;      // 0..15 -> 8 rows each
    int tx = tid & 15;      // 0..15 -> 4 cols each
    float acc[8][4];
#pragma unroll
    for (int u = 0; u < 8; u++)
#pragma unroll
        for (int v = 0; v < 4; v++) acc[u][v] = 0.f;

    int kTiles = (K + BK - 1) / BK;
    for (int kt = 0; kt < kTiles; kt++) {
        int k0 = kt * BK;
        // load A tile (128x16), transposed into As[col][row]; 2 float4 per thread
#pragma unroll
        for (int it = 0; it < 2; it++) {
            int slot = tid + it * 256;          // 0..511
            int row = slot >> 2;
            int cv = (slot & 3) * 4;
            float4 v = make_float4(0.f, 0.f, 0.f, 0.f);
            if (k0 + cv < K)                    // K%4==0 so full float4 is valid
                v = *reinterpret_cast<const float4*>(&A[(long)(bm + row) * K + k0 + cv]);
            As[cv + 0][row] = v.x;
            As[cv + 1][row] = v.y;
            As[cv + 2][row] = v.z;
            As[cv + 3][row] = v.w;
        }
        // load B tile (16x64); 1 float4 per thread
        {
            int row = tid >> 4;
            int cv = (tid & 15) * 4;
            float4 v = make_float4(0.f, 0.f, 0.f, 0.f);
            if (k0 + row < K && bn + cv < N)    // N%4==0
                v = *reinterpret_cast<const float4*>(&Bw[(long)(k0 + row) * N + bn + cv]);
            *reinterpret_cast<float4*>(&Bs[row][cv]) = v;
        }
        __syncthreads();
#pragma unroll
        for (int kk = 0; kk < BK; kk++) {
            float a0[8], b0[4];
#pragma unroll
            for (int u = 0; u < 8; u++) a0[u] = As[kk][ty * 8 + u];
#pragma unroll
            for (int v = 0; v < 4; v++) b0[v] = Bs[kk][tx * 4 + v];
#pragma unroll
            for (int u = 0; u < 8; u++)
#pragma unroll
                for (int v = 0; v < 4; v++) acc[u][v] = fmaf(a0[u], b0[v], acc[u][v]);
        }
        __syncthreads();
    }
    // epilogue
#pragma unroll
    for (int u = 0; u < 8; u++) {
        int gm = bm + ty * 8 + u;
#pragma unroll
        for (int v = 0; v < 4; v++) {
            int gn = bn + tx * 4 + v;
            if (gn < N) {
                float val = acc[u][v] * sc[gn] + sh[gn];
                C[(long)gm * ldc + cofs + gn] = (val > 0.f) ? val : 0.f;
            }
        }
    }
}

// ---------------- final fc: [B,100] @ [100,1] + b ----------------
__global__ void k_final(const float* __restrict__ Cc, const float* __restrict__ w,
                        const float* __restrict__ b, float* __restrict__ out) {
    int m = blockIdx.x * blockDim.x + threadIdx.x;
    if (m >= BB) return;
    float s = b[0];
#pragma unroll 4
    for (int j = 0; j < 100; j++) s = fmaf(Cc[(long)m * 100 + j], w[j], s);
    out[m] = s;
}

// ---------------- launch ----------------
extern "C" void kernel_launch(void* const* d_in, const int* in_sizes, int n_in,
                              void* d_out, int out_size) {
    const float* x      = (const float*)d_in[0];
    const int*   ei     = (const int*)d_in[1];
    const int*   batch  = (const int*)d_in[2];
    const float* fp     = (const float*)d_in[3];
    const float* tvf    = (const float*)d_in[4];
    const float* W1     = (const float*)d_in[5];
    const float* as1    = (const float*)d_in[6];
    const float* ad1    = (const float*)d_in[7];
    const float* b1     = (const float*)d_in[8];
    const float* W2     = (const float*)d_in[9];
    const float* as2    = (const float*)d_in[10];
    const float* ad2    = (const float*)d_in[11];
    const float* b2     = (const float*)d_in[12];
    const float* fc1_w  = (const float*)d_in[13];
    const float* fc1_b  = (const float*)d_in[14];
    const float* bn1    = (const float*)d_in[15];
    const float* fc2_w  = (const float*)d_in[16];
    const float* fc2_b  = (const float*)d_in[17];
    const float* bn2    = (const float*)d_in[18];
    const float* fc3_w  = (const float*)d_in[19];
    const float* fc3_b  = (const float*)d_in[20];
    const float* bn3    = (const float*)d_in[21];
    const float* fc4_w  = (const float*)d_in[22];
    const float* fc4_b  = (const float*)d_in[23];
    const float* bn4    = (const float*)d_in[24];
    const float* fcc1_w = (const float*)d_in[25];
    const float* fcc1_b = (const float*)d_in[26];
    const float* bnc    = (const float*)d_in[27];
    const float* fcc2_w = (const float*)d_in[28];
    const float* fcc2_b = (const float*)d_in[29];
    float* out = (float*)d_out;

    int E = in_sizes[1] / 2;

    void *p_h, *p_g, *p_s, *p_t, *p_fp1, *p_tv1, *p_comb, *p_c1, *p_sc, *p_sh;
    cudaGetSymbolAddress(&p_h, d_hbuf);
    cudaGetSymbolAddress(&p_g, d_gbuf);
    cudaGetSymbolAddress(&p_s, d_sv);
    cudaGetSymbolAddress(&p_t, d_tvv);
    cudaGetSymbolAddress(&p_fp1, d_fp1);
    cudaGetSymbolAddress(&p_tv1, d_tv1);
    cudaGetSymbolAddress(&p_comb, d_comb);
    cudaGetSymbolAddress(&p_c1, d_c1);
    cudaGetSymbolAddress(&p_sc, d_scl);
    cudaGetSymbolAddress(&p_sh, d_shf);
    float* hbuf = (float*)p_h;  float* gbuf = (float*)p_g;
    float* sv = (float*)p_s;    float* tv = (float*)p_t;
    float* fp1 = (float*)p_fp1; float* tv1 = (float*)p_tv1;
    float* comb = (float*)p_comb; float* c1 = (float*)p_c1;
    float* scl = (float*)p_sc;  float* shf = (float*)p_sh;

    // ---- CSR build ----
    k_init_deg<<<(NN + 255) / 256, 256>>>();
    k_count<<<(E + 255) / 256, 256>>>(ei, E);
    k_blocksum<<<512, 1024>>>();
    k_scan_bsums<<<1, 512>>>();
    k_scan_final<<<512, 1024>>>();
    k_fill<<<(E + NN + 255) / 256, 256>>>(ei, E);

    // ---- GAT layer 1 (14 -> 14) ----
    k_node_linear<14, 14, 14, 16><<<(NN + 255) / 256, 256>>>(x, W1, as1, ad1, hbuf, sv, tv);
    k_gat_agg<14, 16, 16><<<(NN * 32 + 255) / 256, 256>>>(hbuf, sv, tv, b1, gbuf);

    // ---- GAT layer 2 (14 -> 32) ----
    k_node_linear<14, 16, 32, 32><<<(NN + 255) / 256, 256>>>(gbuf, W2, as2, ad2, hbuf, sv, tv);
    k_gat_agg<32, 32, 32><<<(NN * 32 + 255) / 256, 256>>>(hbuf, sv, tv, b2, gbuf);

    // ---- pool -> comb[:, 0:32] ----
    k_pool<<<(BB * 32 + 255) / 256, 256>>>(batch, gbuf, comb);

    // ---- BN/bias fold ----
    k_prep<<<2, 256>>>(fc1_b, bn1, 400, scl + 0, shf + 0);
    k_prep<<<1, 256>>>(fc2_b, bn2, 200, scl + 400, shf + 400);
    k_prep<<<2, 256>>>(fc3_b, bn3, 400, scl + 600, shf + 600);
    k_prep<<<1, 256>>>(fc4_b, bn4, 200, scl + 1000, shf + 1000);
    k_prep<<<1, 128>>>(fcc1_b, bnc, 100, scl + 1200, shf + 1200);

    // ---- MLP branches ----
    dim3 g1((400 + 63) / 64, BB / 128);
    k_sgemm<<<g1, 256>>>(fp, fc1_w, fp1, BB, 400, 1024, 400, 0, scl + 0, shf + 0);
    dim3 g2((200 + 63) / 64, BB / 128);
    k_sgemm<<<g2, 256>>>(fp1, fc2_w, comb, BB, 200, 400, COMBW, 32, scl + 400, shf + 400);
    dim3 g3((400 + 63) / 64, BB / 128);
    k_sgemm<<<g3, 256>>>(tvf, fc3_w, tv1, BB, 400, 256, 400, 0, scl + 600, shf + 600);
    dim3 g4((200 + 63) / 64, BB / 128);
    k_sgemm<<<g4, 256>>>(tv1, fc4_w, comb, BB, 200, 400, COMBW, 232, scl + 1000, shf + 1000);

    // ---- combined head ----
    dim3 g5((100 + 63) / 64, BB / 128);
    k_sgemm<<<g5, 256>>>(comb, fcc1_w, c1, BB, 100, COMBW, 100, 0, scl + 1200, shf + 1200);
    k_final<<<(BB + 127) / 128, 128>>>(c1, fcc2_w, fcc2_b, out);
}

// round 3
// speedup vs baseline: 1.1205x; 1.1205x over previous
#include <cuda_runtime.h>
#include <cuda_bf16.h>
#include <cstdint>
#include <math.h>

#define NN 524288
#define EE 4194304
#define BB 16384
#define SLOPE 0.2f

// ---------------- scratch (device globals; no allocation allowed) ----------------
__device__ int   d_rowptr[NN + 1];
__device__ int   d_cursor[NN];
__device__ int   d_bsum[512];
__device__ int   d_col[EE + NN];
__device__ float d_hbuf[NN * 32];
__device__ float d_gbuf[NN * 32];
__device__ float d_sv[NN];
__device__ float d_tvv[NN];
__device__ float d_c1[BB * 100];
__device__ float d_scl[1300];
__device__ float d_shf[1300];

// bf16 split buffers, one big pool with constexpr offsets
constexpr long O_AFP_H = 0;                         // fp input [16384 x 1024]
constexpr long O_AFP_L = O_AFP_H + 16384L * 1024;
constexpr long O_ATV_H = O_AFP_L + 16384L * 1024;   // tv input [16384 x 256]
constexpr long O_ATV_L = O_ATV_H + 16384L * 256;
constexpr long O_FP1_H = O_ATV_L + 16384L * 256;    // fc1 out [16384 x 416]
constexpr long O_FP1_L = O_FP1_H + 16384L * 416;
constexpr long O_TV1_H = O_FP1_L + 16384L * 416;    // fc3 out [16384 x 416]
constexpr long O_TV1_L = O_TV1_H + 16384L * 416;
constexpr long O_CMB_H = O_TV1_L + 16384L * 416;    // comb [16384 x 448]
constexpr long O_CMB_L = O_CMB_H + 16384L * 448;
constexpr long O_W1_H  = O_CMB_L + 16384L * 448;    // w1t [400 x 1024]
constexpr long O_W1_L  = O_W1_H + 400L * 1024;
constexpr long O_W2_H  = O_W1_L + 400L * 1024;      // w2t [200 x 416]
constexpr long O_W2_L  = O_W2_H + 200L * 416;
constexpr long O_W3_H  = O_W2_L + 200L * 416;       // w3t [400 x 256]
constexpr long O_W3_L  = O_W3_H + 400L * 256;
constexpr long O_W4_H  = O_W3_L + 400L * 256;       // w4t [200 x 416]
constexpr long O_W4_L  = O_W4_H + 200L * 416;
constexpr long O_WC_H  = O_W4_L + 200L * 416;       // wct [100 x 448]
constexpr long O_WC_L  = O_WC_H + 100L * 448;
constexpr long O_END   = O_WC_L + 100L * 448;
__device__ __nv_bfloat16 g_bf[O_END];

// ---------------- CSR build ----------------
__global__ void k_init_deg() {
    int i = blockIdx.x * blockDim.x + threadIdx.x;
    if (i < NN) d_cursor[i] = 1;
}

__global__ void k_count(const int* __restrict__ ei, int E) {
    int e = blockIdx.x * blockDim.x + threadIdx.x;
    if (e >= E) return;
    atomicAdd(&d_cursor[ei[E + e]], 1);
}

__global__ void k_blocksum() {
    __shared__ int s[1024];
    int i = blockIdx.x * 1024 + threadIdx.x;
    s[threadIdx.x] = d_cursor[i];
    __syncthreads();
    for (int o = 512; o > 0; o >>= 1) {
        if (threadIdx.x < o) s[threadIdx.x] += s[threadIdx.x + o];
        __syncthreads();
    }
    if (threadIdx.x == 0) d_bsum[blockIdx.x] = s[0];
}

__global__ void k_scan_bsums() {
    __shared__ int s[512];
    int tid = threadIdx.x;
    int v = d_bsum[tid];
    s[tid] = v;
    __syncthreads();
    for (int o = 1; o < 512; o <<= 1) {
        int t = (tid >= o) ? s[tid - o] : 0;
        __syncthreads();
        s[tid] += t;
        __syncthreads();
    }
    d_bsum[tid] = s[tid] - v;
}

__global__ void k_scan_final() {
    __shared__ int s[1024];
    int tid = threadIdx.x;
    int i = blockIdx.x * 1024 + tid;
    int v = d_cursor[i];
    s[tid] = v;
    __syncthreads();
    for (int o = 1; o < 1024; o <<= 1) {
        int t = (tid >= o) ? s[tid - o] : 0;
        __syncthreads();
        s[tid] += t;
        __syncthreads();
    }
    int ex = s[tid] - v + d_bsum[blockIdx.x];
    d_rowptr[i] = ex;
    d_cursor[i] = ex;
    if (i == NN - 1) d_rowptr[NN] = ex + v;
}

__global__ void k_fill(const int* __restrict__ ei, int E) {
    int e = blockIdx.x * blockDim.x + threadIdx.x;
    if (e >= E + NN) return;
    int src, dst;
    if (e < E) { src = ei[e]; dst = ei[E + e]; }
    else       { src = dst = e - E; }
    int pos = atomicAdd(&d_cursor[dst], 1);
    d_col[pos] = src;
}

// ---------------- node-wise linear ----------------
template <int CIN, int CINS, int COUT, int COUTS>
__global__ void k_node_linear(const float* __restrict__ X, const float* __restrict__ W,
                              const float* __restrict__ asrc, const float* __restrict__ adst,
                              float* __restrict__ H, float* __restrict__ S, float* __restrict__ T) {
    __shared__ float sW[CIN * COUT];
    __shared__ float sa[COUT], sd[COUT];
    for (int i = threadIdx.x; i < CIN * COUT; i += blockDim.x) sW[i] = W[i];
    for (int i = threadIdx.x; i < COUT; i += blockDim.x) { sa[i] = asrc[i]; sd[i] = adst[i]; }
    __syncthreads();
    int i = blockIdx.x * blockDim.x + threadIdx.x;
    if (i >= NN) return;
    float xr[CIN];
#pragma unroll
    for (int k = 0; k < CIN; k++) xr[k] = X[(long)i * CINS + k];
    float acc[COUT];
#pragma unroll
    for (int j = 0; j < COUT; j++) acc[j] = 0.f;
#pragma unroll
    for (int k = 0; k < CIN; k++) {
        float xv = xr[k];
#pragma unroll
        for (int j = 0; j < COUT; j++) acc[j] = fmaf(xv, sW[k * COUT + j], acc[j]);
    }
    float s = 0.f, t = 0.f;
#pragma unroll
    for (int j = 0; j < COUT; j++) { s = fmaf(acc[j], sa[j], s); t = fmaf(acc[j], sd[j], t); }
#pragma unroll
    for (int j = 0; j < COUTS; j++)
        H[(long)i * COUTS + j] = (j < COUT) ? acc[j] : 0.f;
    S[i] = s;
    T[i] = t;
}

// ---------------- GAT aggregation ----------------
template <int C, int HS, int OUTS>
__global__ void k_gat_agg(const float* __restrict__ H, const float* __restrict__ S,
                          const float* __restrict__ T, const float* __restrict__ bias,
                          float* __restrict__ OUT) {
    int warp = (blockIdx.x * blockDim.x + threadIdx.x) >> 5;
    int lane = threadIdx.x & 31;
    if (warp >= NN) return;
    int p0 = d_rowptr[warp];
    int p1 = d_rowptr[warp + 1];
    float ti = T[warp];
    float m = -INFINITY, sum = 0.f, acc = 0.f;
    for (int p = p0; p < p1; p++) {
        int src = __ldg(&d_col[p]);
        float e = S[src] + ti;
        e = (e > 0.f) ? e : SLOPE * e;
        float hv = (lane < C) ? H[(long)src * HS + lane] : 0.f;
        if (e > m) {
            float sc = __expf(m - e);
            sum = sum * sc + 1.f;
            acc = acc * sc + hv;
            m = e;
        } else {
            float w = __expf(e - m);
            sum += w;
            acc = fmaf(w, hv, acc);
        }
    }
    if (lane < C) {
        float v = acc / sum + bias[lane];
        OUT[(long)warp * OUTS + lane] = (v > 0.f) ? v : 0.f;
    } else if (lane < OUTS) {
        OUT[(long)warp * OUTS + lane] = 0.f;
    }
}

// ---------------- pool: warp per graph -> comb hi/lo bf16 ----------------
__global__ void k_pool(const int* __restrict__ batch, const float* __restrict__ G,
                       __nv_bfloat16* __restrict__ ch, __nv_bfloat16* __restrict__ cl) {
    int warp = (blockIdx.x * blockDim.x + threadIdx.x) >> 5;
    int lane = threadIdx.x & 31;
    if (warp >= BB) return;
    int b = warp;
    int lo = 0, hi = NN;
    while (lo < hi) { int mid = (lo + hi) >> 1; if (batch[mid] < b) lo = mid + 1; else hi = mid; }
    int start = lo;
    hi = NN;
    while (lo < hi) { int mid = (lo + hi) >> 1; if (batch[mid] < b + 1) lo = mid + 1; else hi = mid; }
    int end = lo;
    float s = 0.f;
    for (int r = start; r < end; r++) s += G[(long)r * 32 + lane];
    __nv_bfloat16 h = __float2bfloat16(s);
    ch[(long)b * 448 + lane] = h;
    cl[(long)b * 448 + lane] = __float2bfloat16(s - __bfloat162float(h));
}

// ---------------- BN/bias fold ----------------
__global__ void k_prep(const float* __restrict__ bias, const float* __restrict__ bn, int n,
                       float* __restrict__ sc, float* __restrict__ sh) {
    int j = blockIdx.x * blockDim.x + threadIdx.x;
    if (j >= n) return;
    float g = bn[j], be = bn[n + j], mu = bn[2 * n + j], va = bn[3 * n + j];
    float s = g * rsqrtf(va + 1e-5f);
    sc[j] = s;
    sh[j] = (bias[j] - mu) * s + be;
}

// ---------------- split conversions ----------------
__global__ void k_asplit(const float* __restrict__ in, __nv_bfloat16* __restrict__ h,
                         __nv_bfloat16* __restrict__ l, long n) {
    long i = (long)blockIdx.x * blockDim.x + threadIdx.x;
    if (i >= n) return;
    float v = in[i];
    __nv_bfloat16 hv = __float2bfloat16(v);
    h[i] = hv;
    l[i] = __float2bfloat16(v - __bfloat162float(hv));
}

// weight [K][N] -> transposed split padded [N][Kp]
__global__ void k_wsplit(const float* __restrict__ w, int K, int N, int Kp,
                         __nv_bfloat16* __restrict__ th, __nv_bfloat16* __restrict__ tl) {
    long i = (long)blockIdx.x * blockDim.x + threadIdx.x;
    if (i >= (long)N * Kp) return;
    int n = (int)(i / Kp);
    int k = (int)(i % Kp);
    float v = (k < K) ? w[(long)k * N + n] : 0.f;
    __nv_bfloat16 hv = __float2bfloat16(v);
    th[i] = hv;
    tl[i] = __float2bfloat16(v - __bfloat162float(hv));
}

// ---------------- tensor-core GEMM (split-bf16, 3-MMA) ----------------
#define LDSM4(r0, r1, r2, r3, addr) \
    asm volatile("ldmatrix.sync.aligned.m8n8.x4.shared.b16 {%0,%1,%2,%3}, [%4];" \
                 : "=r"(r0), "=r"(r1), "=r"(r2), "=r"(r3) : "r"(addr))

#define MMA16816(c, a, b) \
    asm volatile("mma.sync.aligned.m16n8k16.row.col.f32.bf16.bf16.f32 " \
                 "{%0,%1,%2,%3}, {%4,%5,%6,%7}, {%8,%9}, {%0,%1,%2,%3};" \
                 : "+f"(c[0]), "+f"(c[1]), "+f"(c[2]), "+f"(c[3]) \
                 : "r"(a[0]), "r"(a[1]), "r"(a[2]), "r"(a[3]), "r"(b[0]), "r"(b[1]))

// C = relu((A @ B^T) * sc + sh); A [16384 x Kp] row-major bf16 (hi/lo),
// B [N x Kp] row-major bf16 (hi/lo, i.e. weight transposed). BM=128 BN=64 BK=32.
__global__ __launch_bounds__(256) void k_mma(
    const __nv_bfloat16* __restrict__ Ah, const __nv_bfloat16* __restrict__ Al,
    const __nv_bfloat16* __restrict__ Bh, const __nv_bfloat16* __restrict__ Bl,
    int Kp, int N,
    const float* __restrict__ sc, const float* __restrict__ sh,
    float* __restrict__ outF, __nv_bfloat16* __restrict__ outH, __nv_bfloat16* __restrict__ outL,
    int ldc, int cofs, int Nstore, int Nzero) {
    __shared__ __nv_bfloat16 As[2][128][48];
    __shared__ __nv_bfloat16 Bs[2][64][48];
    int tid = threadIdx.x;
    int lane = tid & 31, warp = tid >> 5;
    int wm = warp >> 1, wn = warp & 1;
    int bm = blockIdx.y * 128, bn = blockIdx.x * 64;

    float acc[2][4][4];
#pragma unroll
    for (int mi = 0; mi < 2; mi++)
#pragma unroll
        for (int ni = 0; ni < 4; ni++)
#pragma unroll
            for (int r = 0; r < 4; r++) acc[mi][ni][r] = 0.f;

    int ar = tid >> 2;           // 0..63
    int ac = (tid & 3) * 8;      // 0,8,16,24

    for (int k0 = 0; k0 < Kp; k0 += 32) {
        // load A tile (hi/lo), 128x32
#pragma unroll
        for (int s = 0; s < 2; s++) {
            const __nv_bfloat16* src = s ? Al : Ah;
#pragma unroll
            for (int rr = 0; rr < 2; rr++) {
                int row = ar + rr * 64;
                uint4 v = *reinterpret_cast<const uint4*>(&src[(long)(bm + row) * Kp + k0 + ac]);
                *reinterpret_cast<uint4*>(&As[s][row][ac]) = v;
            }
        }
        // load B tile (hi/lo), 64x32, row-guarded
#pragma unroll
        for (int s = 0; s < 2; s++) {
            const __nv_bfloat16* src = s ? Bl : Bh;
            uint4 v = make_uint4(0, 0, 0, 0);
            if (bn + ar < N)
                v = *reinterpret_cast<const uint4*>(&src[(long)(bn + ar) * Kp + k0 + ac]);
            *reinterpret_cast<uint4*>(&Bs[s][ar][ac]) = v;
        }
        __syncthreads();
#pragma unroll
        for (int ks = 0; ks < 2; ks++) {
            uint32_t ah[2][4], al[2][4], bh[4][2], bl[4][2];
#pragma unroll
            for (int mi = 0; mi < 2; mi++) {
                int row = wm * 32 + mi * 16 + (lane & 15);
                int col = ks * 16 + (lane >> 4) * 8;
                uint32_t ad = (uint32_t)__cvta_generic_to_shared(&As[0][row][col]);
                LDSM4(ah[mi][0], ah[mi][1], ah[mi][2], ah[mi][3], ad);
                ad = (uint32_t)__cvta_generic_to_shared(&As[1][row][col]);
                LDSM4(al[mi][0], al[mi][1], al[mi][2], al[mi][3], ad);
            }
#pragma unroll
            for (int nh = 0; nh < 2; nh++) {
                int p = lane >> 3, l7 = lane & 7;
                int nrow = wn * 32 + nh * 16 + (p >> 1) * 8 + l7;
                int col = ks * 16 + (p & 1) * 8;
                uint32_t ad = (uint32_t)__cvta_generic_to_shared(&Bs[0][nrow][col]);
                LDSM4(bh[2 * nh][0], bh[2 * nh][1], bh[2 * nh + 1][0], bh[2 * nh + 1][1], ad);
                ad = (uint32_t)__cvta_generic_to_shared(&Bs[1][nrow][col]);
                LDSM4(bl[2 * nh][0], bl[2 * nh][1], bl[2 * nh + 1][0], bl[2 * nh + 1][1], ad);
            }
#pragma unroll
            for (int mi = 0; mi < 2; mi++)
#pragma unroll
                for (int ni = 0; ni < 4; ni++) {
                    MMA16816(acc[mi][ni], ah[mi], bh[ni]);
                    MMA16816(acc[mi][ni], ah[mi], bl[ni]);
                    MMA16816(acc[mi][ni], al[mi], bh[ni]);
                }
        }
        __syncthreads();
    }

    // epilogue: scale/shift + relu, write fp32 and/or bf16 hi/lo
    int g = lane >> 2, t2 = (lane & 3) * 2;
#pragma unroll
    for (int mi = 0; mi < 2; mi++)
#pragma unroll
        for (int ni = 0; ni < 4; ni++)
#pragma unroll
            for (int r = 0; r < 4; r++) {
                int gm = bm + wm * 32 + mi * 16 + g + ((r >> 1) * 8);
                int gn = bn + wn * 32 + ni * 8 + t2 + (r & 1);
                if (gn < Nzero) {
                    float val = 0.f;
                    if (gn < Nstore) {
                        val = acc[mi][ni][r] * sc[gn] + sh[gn];
                        val = (val > 0.f) ? val : 0.f;
                    }
                    long o = (long)gm * ldc + cofs + gn;
                    if (outF) outF[o] = val;
                    if (outH) {
                        __nv_bfloat16 hv = __float2bfloat16(val);
                        outH[o] = hv;
                        outL[o] = __float2bfloat16(val - __bfloat162float(hv));
                    }
                }
            }
}

// ---------------- final fc ----------------
__global__ void k_final(const float* __restrict__ Cc, const float* __restrict__ w,
                        const float* __restrict__ b, float* __restrict__ out) {
    int m = blockIdx.x * blockDim.x + threadIdx.x;
    if (m >= BB) return;
    float s = b[0];
#pragma unroll 4
    for (int j = 0; j < 100; j++) s = fmaf(Cc[(long)m * 100 + j], w[j], s);
    out[m] = s;
}

// ---------------- launch ----------------
extern "C" void kernel_launch(void* const* d_in, const int* in_sizes, int n_in,
                              void* d_out, int out_size) {
    const float* x      = (const float*)d_in[0];
    const int*   ei     = (const int*)d_in[1];
    const int*   batch  = (const int*)d_in[2];
    const float* fp     = (const float*)d_in[3];
    const float* tvf    = (const float*)d_in[4];
    const float* W1     = (const float*)d_in[5];
    const float* as1    = (const float*)d_in[6];
    const float* ad1    = (const float*)d_in[7];
    const float* b1     = (const float*)d_in[8];
    const float* W2     = (const float*)d_in[9];
    const float* as2    = (const float*)d_in[10];
    const float* ad2    = (const float*)d_in[11];
    const float* b2     = (const float*)d_in[12];
    const float* fc1_w  = (const float*)d_in[13];
    const float* fc1_b  = (const float*)d_in[14];
    const float* bn1    = (const float*)d_in[15];
    const float* fc2_w  = (const float*)d_in[16];
    const float* fc2_b  = (const float*)d_in[17];
    const float* bn2    = (const float*)d_in[18];
    const float* fc3_w  = (const float*)d_in[19];
    const float* fc3_b  = (const float*)d_in[20];
    const float* bn3    = (const float*)d_in[21];
    const float* fc4_w  = (const float*)d_in[22];
    const float* fc4_b  = (const float*)d_in[23];
    const float* bn4    = (const float*)d_in[24];
    const float* fcc1_w = (const float*)d_in[25];
    const float* fcc1_b = (const float*)d_in[26];
    const float* bnc    = (const float*)d_in[27];
    const float* fcc2_w = (const float*)d_in[28];
    const float* fcc2_b = (const float*)d_in[29];
    float* out = (float*)d_out;

    int E = in_sizes[1] / 2;

    void *p_h, *p_g, *p_s, *p_t, *p_c1, *p_sc, *p_sh, *p_bf;
    cudaGetSymbolAddress(&p_h, d_hbuf);
    cudaGetSymbolAddress(&p_g, d_gbuf);
    cudaGetSymbolAddress(&p_s, d_sv);
    cudaGetSymbolAddress(&p_t, d_tvv);
    cudaGetSymbolAddress(&p_c1, d_c1);
    cudaGetSymbolAddress(&p_sc, d_scl);
    cudaGetSymbolAddress(&p_sh, d_shf);
    cudaGetSymbolAddress(&p_bf, g_bf);
    float* hbuf = (float*)p_h;  float* gbuf = (float*)p_g;
    float* sv = (float*)p_s;    float* tv = (float*)p_t;
    float* c1 = (float*)p_c1;
    float* scl = (float*)p_sc;  float* shf = (float*)p_sh;
    __nv_bfloat16* bf = (__nv_bfloat16*)p_bf;

    // ---- CSR build ----
    k_init_deg<<<(NN + 255) / 256, 256>>>();
    k_count<<<(E + 255) / 256, 256>>>(ei, E);
    k_blocksum<<<512, 1024>>>();
    k_scan_bsums<<<1, 512>>>();
    k_scan_final<<<512, 1024>>>();
    k_fill<<<(E + NN + 255) / 256, 256>>>(ei, E);

    // ---- GAT layer 1 (14 -> 14) ----
    k_node_linear<14, 14, 14, 16><<<(NN + 255) / 256, 256>>>(x, W1, as1, ad1, hbuf, sv, tv);
    k_gat_agg<14, 16, 16><<<(NN * 32 + 255) / 256, 256>>>(hbuf, sv, tv, b1, gbuf);

    // ---- GAT layer 2 (14 -> 32) ----
    k_node_linear<14, 16, 32, 32><<<(NN + 255) / 256, 256>>>(gbuf, W2, as2, ad2, hbuf, sv, tv);
    k_gat_agg<32, 32, 32><<<(NN * 32 + 255) / 256, 256>>>(hbuf, sv, tv, b2, gbuf);

    // ---- pool -> comb[:, 0:32] as bf16 hi/lo ----
    k_pool<<<(BB * 32 + 255) / 256, 256>>>(batch, gbuf, bf + O_CMB_H, bf + O_CMB_L);

    // ---- BN/bias fold ----
    k_prep<<<2, 256>>>(fc1_b, bn1, 400, scl + 0, shf + 0);
    k_prep<<<1, 256>>>(fc2_b, bn2, 200, scl + 400, shf + 400);
    k_prep<<<2, 256>>>(fc3_b, bn3, 400, scl + 600, shf + 600);
    k_prep<<<1, 256>>>(fc4_b, bn4, 200, scl + 1000, shf + 1000);
    k_prep<<<1, 128>>>(fcc1_b, bnc, 100, scl + 1200, shf + 1200);

    // ---- activation splits ----
    {
        long n = 16384L * 1024;
        k_asplit<<<(int)((n + 255) / 256), 256>>>(fp, bf + O_AFP_H, bf + O_AFP_L, n);
        n = 16384L * 256;
        k_asplit<<<(int)((n + 255) / 256), 256>>>(tvf, bf + O_ATV_H, bf + O_ATV_L, n);
    }
    // ---- weight transpose + split + pad ----
    k_wsplit<<<(400 * 1024 + 255) / 256, 256>>>(fc1_w, 1024, 400, 1024, bf + O_W1_H, bf + O_W1_L);
    k_wsplit<<<(200 * 416 + 255) / 256, 256>>>(fc2_w, 400, 200, 416, bf + O_W2_H, bf + O_W2_L);
    k_wsplit<<<(400 * 256 + 255) / 256, 256>>>(fc3_w, 256, 400, 256, bf + O_W3_H, bf + O_W3_L);
    k_wsplit<<<(200 * 416 + 255) / 256, 256>>>(fc4_w, 400, 200, 416, bf + O_W4_H, bf + O_W4_L);
    k_wsplit<<<(100 * 448 + 255) / 256, 256>>>(fcc1_w, 432, 100, 448, bf + O_WC_H, bf + O_WC_L);

    // ---- tensor-core GEMMs ----
    // fc1: [16384,1024]x[1024,400] -> fp1 (Kp out = 416, zero pad 400..415)
    k_mma<<<dim3(7, 128), 256>>>(bf + O_AFP_H, bf + O_AFP_L, bf + O_W1_H, bf + O_W1_L,
                                 1024, 400, scl + 0, shf + 0,
                                 nullptr, bf + O_FP1_H, bf + O_FP1_L, 416, 0, 400, 416);
    // fc3: [16384,256]x[256,400] -> tv1
    k_mma<<<dim3(7, 128), 256>>>(bf + O_ATV_H, bf + O_ATV_L, bf + O_W3_H, bf + O_W3_L,
                                 256, 400, scl + 600, shf + 600,
                                 nullptr, bf + O_TV1_H, bf + O_TV1_L, 416, 0, 400, 416);
    // fc2: [16384,416]x[416,200] -> comb[:,32:232]
    k_mma<<<dim3(4, 128), 256>>>(bf + O_FP1_H, bf + O_FP1_L, bf + O_W2_H, bf + O_W2_L,
                                 416, 200, scl + 400, shf + 400,
                                 nullptr, bf + O_CMB_H, bf + O_CMB_L, 448, 32, 200, 200);
    // fc4: [16384,416]x[416,200] -> comb[:,232:432], zero comb[:,432:448]
    k_mma<<<dim3(4, 128), 256>>>(bf + O_TV1_H, bf + O_TV1_L, bf + O_W4_H, bf + O_W4_L,
                                 416, 200, scl + 1000, shf + 1000,
                                 nullptr, bf + O_CMB_H, bf + O_CMB_L, 448, 232, 200, 216);
    // fcc1: [16384,448]x[448,100] -> c1 fp32
    k_mma<<<dim3(2, 128), 256>>>(bf + O_CMB_H, bf + O_CMB_L, bf + O_WC_H, bf + O_WC_L,
                                 448, 100, scl + 1200, shf + 1200,
                                 c1, nullptr, nullptr, 100, 0, 100, 100);

    k_final<<<(BB + 127) / 128, 128>>>(c1, fcc2_w, fcc2_b, out);
}

// round 4
// speedup vs baseline: 1.2383x; 1.1051x over previous
#include <cuda_runtime.h>
#include <cuda_bf16.h>
#include <cstdint>
#include <math.h>

#define NN 524288
#define EE 4194304
#define BB 16384
#define SLOPE 0.2f

// ---------------- scratch (device globals; no allocation allowed) ----------------
__device__ int   d_rowptr[NN + 1];
__device__ int   d_cursor[NN];
__device__ int   d_bsum[512];
__device__ int   d_col[EE + NN];
__device__ float d_hbuf[NN * 32];
__device__ float d_gbuf[NN * 32];
__device__ float d_sv[NN];
__device__ float d_tvv[NN];
__device__ float d_c1[BB * 100];
__device__ float d_scl[1300];
__device__ float d_shf[1300];

// bf16 split buffers (weights padded to 64-row multiples for guard-free loads)
constexpr long O_AFP_H = 0;                         // fp input [16384 x 1024]
constexpr long O_AFP_L = O_AFP_H + 16384L * 1024;
constexpr long O_ATV_H = O_AFP_L + 16384L * 1024;   // tv input [16384 x 256]
constexpr long O_ATV_L = O_ATV_H + 16384L * 256;
constexpr long O_FP1_H = O_ATV_L + 16384L * 256;    // fc1 out [16384 x 416]
constexpr long O_FP1_L = O_FP1_H + 16384L * 416;
constexpr long O_TV1_H = O_FP1_L + 16384L * 416;    // fc3 out [16384 x 416]
constexpr long O_TV1_L = O_TV1_H + 16384L * 416;
constexpr long O_CMB_H = O_TV1_L + 16384L * 416;    // comb [16384 x 448]
constexpr long O_CMB_L = O_CMB_H + 16384L * 448;
constexpr long O_W1_H  = O_CMB_L + 16384L * 448;    // w1t [448 x 1024] (400 valid)
constexpr long O_W1_L  = O_W1_H + 448L * 1024;
constexpr long O_W2_H  = O_W1_L + 448L * 1024;      // w2t [256 x 416] (200 valid)
constexpr long O_W2_L  = O_W2_H + 256L * 416;
constexpr long O_W3_H  = O_W2_L + 256L * 416;       // w3t [448 x 256] (400 valid)
constexpr long O_W3_L  = O_W3_H + 448L * 256;
constexpr long O_W4_H  = O_W3_L + 448L * 256;       // w4t [256 x 416] (200 valid)
constexpr long O_W4_L  = O_W4_H + 256L * 416;
constexpr long O_WC_H  = O_W4_L + 256L * 416;       // wct [128 x 448] (100 valid)
constexpr long O_WC_L  = O_WC_H + 128L * 448;
constexpr long O_END   = O_WC_L + 128L * 448;
__device__ __nv_bfloat16 g_bf[O_END];

// ---------------- CSR build ----------------
__global__ void k_init_deg() {
    int i = blockIdx.x * blockDim.x + threadIdx.x;
    if (i < NN) d_cursor[i] = 1;
}

__global__ void k_count(const int* __restrict__ ei, int E) {
    int e = blockIdx.x * blockDim.x + threadIdx.x;
    if (e >= E) return;
    atomicAdd(&d_cursor[ei[E + e]], 1);
}

__global__ void k_blocksum() {
    __shared__ int s[1024];
    int i = blockIdx.x * 1024 + threadIdx.x;
    s[threadIdx.x] = d_cursor[i];
    __syncthreads();
    for (int o = 512; o > 0; o >>= 1) {
        if (threadIdx.x < o) s[threadIdx.x] += s[threadIdx.x + o];
        __syncthreads();
    }
    if (threadIdx.x == 0) d_bsum[blockIdx.x] = s[0];
}

__global__ void k_scan_bsums() {
    __shared__ int s[512];
    int tid = threadIdx.x;
    int v = d_bsum[tid];
    s[tid] = v;
    __syncthreads();
    for (int o = 1; o < 512; o <<= 1) {
        int t = (tid >= o) ? s[tid - o] : 0;
        __syncthreads();
        s[tid] += t;
        __syncthreads();
    }
    d_bsum[tid] = s[tid] - v;
}

__global__ void k_scan_final() {
    __shared__ int s[1024];
    int tid = threadIdx.x;
    int i = blockIdx.x * 1024 + tid;
    int v = d_cursor[i];
    s[tid] = v;
    __syncthreads();
    for (int o = 1; o < 1024; o <<= 1) {
        int t = (tid >= o) ? s[tid - o] : 0;
        __syncthreads();
        s[tid] += t;
        __syncthreads();
    }
    int ex = s[tid] - v + d_bsum[blockIdx.x];
    d_rowptr[i] = ex;
    d_cursor[i] = ex;
    if (i == NN - 1) d_rowptr[NN] = ex + v;
}

__global__ void k_fill(const int* __restrict__ ei, int E) {
    int e = blockIdx.x * blockDim.x + threadIdx.x;
    if (e >= E + NN) return;
    int src, dst;
    if (e < E) { src = ei[e]; dst = ei[E + e]; }
    else       { src = dst = e - E; }
    int pos = atomicAdd(&d_cursor[dst], 1);
    d_col[pos] = src;
}

// ---------------- node-wise linear ----------------
template <int CIN, int CINS, int COUT, int COUTS>
__global__ void k_node_linear(const float* __restrict__ X, const float* __restrict__ W,
                              const float* __restrict__ asrc, const float* __restrict__ adst,
                              float* __restrict__ H, float* __restrict__ S, float* __restrict__ T) {
    __shared__ float sW[CIN * COUT];
    __shared__ float sa[COUT], sd[COUT];
    for (int i = threadIdx.x; i < CIN * COUT; i += blockDim.x) sW[i] = W[i];
    for (int i = threadIdx.x; i < COUT; i += blockDim.x) { sa[i] = asrc[i]; sd[i] = adst[i]; }
    __syncthreads();
    int i = blockIdx.x * blockDim.x + threadIdx.x;
    if (i >= NN) return;
    float xr[CIN];
#pragma unroll
    for (int k = 0; k < CIN; k++) xr[k] = X[(long)i * CINS + k];
    float acc[COUT];
#pragma unroll
    for (int j = 0; j < COUT; j++) acc[j] = 0.f;
#pragma unroll
    for (int k = 0; k < CIN; k++) {
        float xv = xr[k];
#pragma unroll
        for (int j = 0; j < COUT; j++) acc[j] = fmaf(xv, sW[k * COUT + j], acc[j]);
    }
    float s = 0.f, t = 0.f;
#pragma unroll
    for (int j = 0; j < COUT; j++) { s = fmaf(acc[j], sa[j], s); t = fmaf(acc[j], sd[j], t); }
#pragma unroll
    for (int j = 0; j < COUTS; j++)
        H[(long)i * COUTS + j] = (j < COUT) ? acc[j] : 0.f;
    S[i] = s;
    T[i] = t;
}

// ---------------- GAT aggregation: chunk-4 batched loads + chunked online softmax ----------------
template <int C, int HS, int OUTS>
__global__ void k_gat_agg(const float* __restrict__ H, const float* __restrict__ S,
                          const float* __restrict__ T, const float* __restrict__ bias,
                          float* __restrict__ OUT) {
    int warp = (blockIdx.x * blockDim.x + threadIdx.x) >> 5;
    int lane = threadIdx.x & 31;
    if (warp >= NN) return;
    int p0 = d_rowptr[warp];
    int p1 = d_rowptr[warp + 1];
    float ti = T[warp];
    bool fl = (lane < C);
    float m = -INFINITY, sum = 0.f, acc = 0.f;
    for (int p = p0; p < p1; p += 4) {
        int n = p1 - p;
        int s0 = __ldg(&d_col[p]);
        int s1 = (n > 1) ? __ldg(&d_col[p + 1]) : 0;
        int s2 = (n > 2) ? __ldg(&d_col[p + 2]) : 0;
        int s3 = (n > 3) ? __ldg(&d_col[p + 3]) : 0;
        float e0 = S[s0] + ti;
        float e1 = (n > 1) ? S[s1] + ti : -INFINITY;
        float e2 = (n > 2) ? S[s2] + ti : -INFINITY;
        float e3 = (n > 3) ? S[s3] + ti : -INFINITY;
        float h0 = fl ? H[(long)s0 * HS + lane] : 0.f;
        float h1 = (fl && n > 1) ? H[(long)s1 * HS + lane] : 0.f;
        float h2 = (fl && n > 2) ? H[(long)s2 * HS + lane] : 0.f;
        float h3 = (fl && n > 3) ? H[(long)s3 * HS + lane] : 0.f;
        e0 = (e0 > 0.f) ? e0 : SLOPE * e0;
        e1 = (e1 > 0.f) ? e1 : SLOPE * e1;
        e2 = (e2 > 0.f) ? e2 : SLOPE * e2;
        e3 = (e3 > 0.f) ? e3 : SLOPE * e3;
        float cm = fmaxf(fmaxf(e0, e1), fmaxf(e2, e3));
        if (cm > m) {
            float sc = __expf(m - cm);   // first chunk: exp(-inf)=0
            sum *= sc;
            acc *= sc;
            m = cm;
        }
        float w0 = __expf(e0 - m);
        float w1 = __expf(e1 - m);
        float w2 = __expf(e2 - m);
        float w3 = __expf(e3 - m);
        sum += (w0 + w1) + (w2 + w3);
        acc = fmaf(w0, h0, acc);
        acc = fmaf(w1, h1, acc);
        acc = fmaf(w2, h2, acc);
        acc = fmaf(w3, h3, acc);
    }
    if (fl) {
        float v = acc / sum + bias[lane];
        OUT[(long)warp * OUTS + lane] = (v > 0.f) ? v : 0.f;
    } else if (lane < OUTS) {
        OUT[(long)warp * OUTS + lane] = 0.f;
    }
}

// ---------------- pool: warp per graph -> comb hi/lo bf16 ----------------
__global__ void k_pool(const int* __restrict__ batch, const float* __restrict__ G,
                       __nv_bfloat16* __restrict__ ch, __nv_bfloat16* __restrict__ cl) {
    int warp = (blockIdx.x * blockDim.x + threadIdx.x) >> 5;
    int lane = threadIdx.x & 31;
    if (warp >= BB) return;
    int b = warp;
    int lo = 0, hi = NN;
    while (lo < hi) { int mid = (lo + hi) >> 1; if (batch[mid] < b) lo = mid + 1; else hi = mid; }
    int start = lo;
    hi = NN;
    while (lo < hi) { int mid = (lo + hi) >> 1; if (batch[mid] < b + 1) lo = mid + 1; else hi = mid; }
    int end = lo;
    float s = 0.f;
    for (int r = start; r < end; r++) s += G[(long)r * 32 + lane];
    __nv_bfloat16 h = __float2bfloat16(s);
    ch[(long)b * 448 + lane] = h;
    cl[(long)b * 448 + lane] = __float2bfloat16(s - __bfloat162float(h));
}

// ---------------- BN/bias fold ----------------
__global__ void k_prep(const float* __restrict__ bias, const float* __restrict__ bn, int n,
                       float* __restrict__ sc, float* __restrict__ sh) {
    int j = blockIdx.x * blockDim.x + threadIdx.x;
    if (j >= n) return;
    float g = bn[j], be = bn[n + j], mu = bn[2 * n + j], va = bn[3 * n + j];
    float s = g * rsqrtf(va + 1e-5f);
    sc[j] = s;
    sh[j] = (bias[j] - mu) * s + be;
}

// ---------------- split conversions (vectorized x4) ----------------
__global__ void k_asplit(const float* __restrict__ in, __nv_bfloat16* __restrict__ h,
                         __nv_bfloat16* __restrict__ l, long n4) {
    long i = (long)blockIdx.x * blockDim.x + threadIdx.x;
    if (i >= n4) return;
    float4 v = *reinterpret_cast<const float4*>(in + i * 4);
    __nv_bfloat16 h0 = __float2bfloat16(v.x), h1 = __float2bfloat16(v.y);
    __nv_bfloat16 h2 = __float2bfloat16(v.z), h3 = __float2bfloat16(v.w);
    __nv_bfloat162* hp = reinterpret_cast<__nv_bfloat162*>(h + i * 4);
    hp[0] = __nv_bfloat162(h0, h1);
    hp[1] = __nv_bfloat162(h2, h3);
    __nv_bfloat162* lp = reinterpret_cast<__nv_bfloat162*>(l + i * 4);
    lp[0] = __nv_bfloat162(__float2bfloat16(v.x - __bfloat162float(h0)),
                           __float2bfloat16(v.y - __bfloat162float(h1)));
    lp[1] = __nv_bfloat162(__float2bfloat16(v.z - __bfloat162float(h2)),
                           __float2bfloat16(v.w - __bfloat162float(h3)));
}

// weight [K][N] -> transposed split, padded to [Np][Kp] (zero beyond N/K)
__global__ void k_wsplit(const float* __restrict__ w, int K, int N, int Kp, int Np,
                         __nv_bfloat16* __restrict__ th, __nv_bfloat16* __restrict__ tl) {
    long i = (long)blockIdx.x * blockDim.x + threadIdx.x;
    if (i >= (long)Np * Kp) return;
    int n = (int)(i / Kp);
    int k = (int)(i % Kp);
    float v = (k < K && n < N) ? w[(long)k * N + n] : 0.f;
    __nv_bfloat16 hv = __float2bfloat16(v);
    th[i] = hv;
    tl[i] = __float2bfloat16(v - __bfloat162float(hv));
}

// ---------------- tensor-core GEMM (split-bf16, 3-MMA, cp.async 2-stage pipeline) ----------------
#define LDSM4(r0, r1, r2, r3, addr) \
    asm volatile("ldmatrix.sync.aligned.m8n8.x4.shared.b16 {%0,%1,%2,%3}, [%4];" \
                 : "=r"(r0), "=r"(r1), "=r"(r2), "=r"(r3) : "r"(addr))

#define MMA16816(c, a, b) \
    asm volatile("mma.sync.aligned.m16n8k16.row.col.f32.bf16.bf16.f32 " \
                 "{%0,%1,%2,%3}, {%4,%5,%6,%7}, {%8,%9}, {%0,%1,%2,%3};" \
                 : "+f"(c[0]), "+f"(c[1]), "+f"(c[2]), "+f"(c[3]) \
                 : "r"(a[0]), "r"(a[1]), "r"(a[2]), "r"(a[3]), "r"(b[0]), "r"(b[1]))

#define CPA16(d, s) asm volatile("cp.async.cg.shared.global [%0], [%1], 16;" :: "r"(d), "l"(s))
#define CP_COMMIT   asm volatile("cp.async.commit_group;")
#define CP_WAIT1    asm volatile("cp.async.wait_group 1;")
#define CP_WAIT0    asm volatile("cp.async.wait_group 0;")

// smem layout (bytes): A[stage][hl][128][48] = 49152, then B[stage][hl][64][48] = 24576
#define SM_B_BASE 49152
#define SM_TOTAL  73728

// C = relu((A @ B^T) * sc + sh). A [16384 x Kp] bf16 hi/lo; B [Np x Kp] bf16 hi/lo (padded).
__global__ __launch_bounds__(256) void k_mma(
    const __nv_bfloat16* __restrict__ Ah, const __nv_bfloat16* __restrict__ Al,
    const __nv_bfloat16* __restrict__ Bh, const __nv_bfloat16* __restrict__ Bl,
    int Kp,
    const float* __restrict__ sc, const float* __restrict__ sh,
    float* __restrict__ outF, __nv_bfloat16* __restrict__ outH, __nv_bfloat16* __restrict__ outL,
    int ldc, int cofs, int Nstore, int Nzero) {
    extern __shared__ __nv_bfloat16 dsm[];
    uint32_t sb = (uint32_t)__cvta_generic_to_shared(dsm);
    int tid = threadIdx.x;
    int lane = tid & 31, warp = tid >> 5;
    int wm = warp >> 1, wn = warp & 1;
    int bm = blockIdx.y * 128, bn = blockIdx.x * 64;

    float acc[2][4][4];
#pragma unroll
    for (int mi = 0; mi < 2; mi++)
#pragma unroll
        for (int ni = 0; ni < 4; ni++)
#pragma unroll
            for (int r = 0; r < 4; r++) acc[mi][ni][r] = 0.f;

    int ar = tid >> 2;           // 0..63
    int ac = (tid & 3) * 8;      // 0,8,16,24

    // per-thread global srcs / smem dsts for one stage
    auto issue = [&](int kt, int stg) {
        long k0 = (long)kt * 32 + ac;
#pragma unroll
        for (int hl = 0; hl < 2; hl++) {
            const __nv_bfloat16* sa = hl ? Al : Ah;
#pragma unroll
            for (int rr = 0; rr < 2; rr++) {
                int row = ar + rr * 64;
                const void* g = sa + (long)(bm + row) * Kp + k0;
                uint32_t d = sb + ((((stg * 2 + hl) * 128 + row) * 48 + ac) << 1);
                CPA16(d, g);
            }
            const __nv_bfloat16* sbp = hl ? Bl : Bh;
            const void* gb = sbp + (long)(bn + ar) * Kp + k0;
            uint32_t db = sb + SM_B_BASE + ((((stg * 2 + hl) * 64 + ar) * 48 + ac) << 1);
            CPA16(db, gb);
        }
    };

    int T = Kp >> 5;
    issue(0, 0);
    CP_COMMIT;
    int stg = 0;
    for (int kt = 0; kt < T; kt++) {
        if (kt + 1 < T) {
            issue(kt + 1, stg ^ 1);
            CP_COMMIT;
            CP_WAIT1;
        } else {
            CP_WAIT0;
        }
        __syncthreads();
#pragma unroll
        for (int ks = 0; ks < 2; ks++) {
            uint32_t ah[2][4], al[2][4], bh[4][2], bl[4][2];
#pragma unroll
            for (int mi = 0; mi < 2; mi++) {
                int row = wm * 32 + mi * 16 + (lane & 15);
                int col = ks * 16 + (lane >> 4) * 8;
                uint32_t ad = sb + ((((stg * 2 + 0) * 128 + row) * 48 + col) << 1);
                LDSM4(ah[mi][0], ah[mi][1], ah[mi][2], ah[mi][3], ad);
                ad = sb + ((((stg * 2 + 1) * 128 + row) * 48 + col) << 1);
                LDSM4(al[mi][0], al[mi][1], al[mi][2], al[mi][3], ad);
            }
#pragma unroll
            for (int nh = 0; nh < 2; nh++) {
                int p = lane >> 3, l7 = lane & 7;
                int nrow = wn * 32 + nh * 16 + (p >> 1) * 8 + l7;
                int col = ks * 16 + (p & 1) * 8;
                uint32_t ad = sb + SM_B_BASE + ((((stg * 2 + 0) * 64 + nrow) * 48 + col) << 1);
                LDSM4(bh[2 * nh][0], bh[2 * nh][1], bh[2 * nh + 1][0], bh[2 * nh + 1][1], ad);
                ad = sb + SM_B_BASE + ((((stg * 2 + 1) * 64 + nrow) * 48 + col) << 1);
                LDSM4(bl[2 * nh][0], bl[2 * nh][1], bl[2 * nh + 1][0], bl[2 * nh + 1][1], ad);
            }
#pragma unroll
            for (int mi = 0; mi < 2; mi++)
#pragma unroll
                for (int ni = 0; ni < 4; ni++) {
                    MMA16816(acc[mi][ni], ah[mi], bh[ni]);
                    MMA16816(acc[mi][ni], ah[mi], bl[ni]);
                    MMA16816(acc[mi][ni], al[mi], bh[ni]);
                }
        }
        __syncthreads();
        stg ^= 1;
    }

    // epilogue: scale/shift + relu, write fp32 and/or bf16 hi/lo
    int g = lane >> 2, t2 = (lane & 3) * 2;
#pragma unroll
    for (int mi = 0; mi < 2; mi++)
#pragma unroll
        for (int ni = 0; ni < 4; ni++)
#pragma unroll
            for (int r = 0; r < 4; r++) {
                int gm = bm + wm * 32 + mi * 16 + g + ((r >> 1) * 8);
                int gn = bn + wn * 32 + ni * 8 + t2 + (r & 1);
                if (gn < Nzero) {
                    float val = 0.f;
                    if (gn < Nstore) {
                        val = acc[mi][ni][r] * sc[gn] + sh[gn];
                        val = (val > 0.f) ? val : 0.f;
                    }
                    long o = (long)gm * ldc + cofs + gn;
                    if (outF) outF[o] = val;
                    if (outH) {
                        __nv_bfloat16 hv = __float2bfloat16(val);
                        outH[o] = hv;
                        outL[o] = __float2bfloat16(val - __bfloat162float(hv));
                    }
                }
            }
}

// ---------------- final fc ----------------
__global__ void k_final(const float* __restrict__ Cc, const float* __restrict__ w,
                        const float* __restrict__ b, float* __restrict__ out) {
    int m = blockIdx.x * blockDim.x + threadIdx.x;
    if (m >= BB) return;
    float s = b[0];
#pragma unroll 4
    for (int j = 0; j < 100; j++) s = fmaf(Cc[(long)m * 100 + j], w[j], s);
    out[m] = s;
}

// ---------------- launch ----------------
extern "C" void kernel_launch(void* const* d_in, const int* in_sizes, int n_in,
                              void* d_out, int out_size) {
    const float* x      = (const float*)d_in[0];
    const int*   ei     = (const int*)d_in[1];
    const int*   batch  = (const int*)d_in[2];
    const float* fp     = (const float*)d_in[3];
    const float* tvf    = (const float*)d_in[4];
    const float* W1     = (const float*)d_in[5];
    const float* as1    = (const float*)d_in[6];
    const float* ad1    = (const float*)d_in[7];
    const float* b1     = (const float*)d_in[8];
    const float* W2     = (const float*)d_in[9];
    const float* as2    = (const float*)d_in[10];
    const float* ad2    = (const float*)d_in[11];
    const float* b2     = (const float*)d_in[12];
    const float* fc1_w  = (const float*)d_in[13];
    const float* fc1_b  = (const float*)d_in[14];
    const float* bn1    = (const float*)d_in[15];
    const float* fc2_w  = (const float*)d_in[16];
    const float* fc2_b  = (const float*)d_in[17];
    const float* bn2    = (const float*)d_in[18];
    const float* fc3_w  = (const float*)d_in[19];
    const float* fc3_b  = (const float*)d_in[20];
    const float* bn3    = (const float*)d_in[21];
    const float* fc4_w  = (const float*)d_in[22];
    const float* fc4_b  = (const float*)d_in[23];
    const float* bn4    = (const float*)d_in[24];
    const float* fcc1_w = (const float*)d_in[25];
    const float* fcc1_b = (const float*)d_in[26];
    const float* bnc    = (const float*)d_in[27];
    const float* fcc2_w = (const float*)d_in[28];
    const float* fcc2_b = (const float*)d_in[29];
    float* out = (float*)d_out;

    int E = in_sizes[1] / 2;

    static int smem_set = 0;
    if (!smem_set) {
        cudaFuncSetAttribute(k_mma, cudaFuncAttributeMaxDynamicSharedMemorySize, SM_TOTAL);
        smem_set = 1;
    }

    void *p_h, *p_g, *p_s, *p_t, *p_c1, *p_sc, *p_sh, *p_bf;
    cudaGetSymbolAddress(&p_h, d_hbuf);
    cudaGetSymbolAddress(&p_g, d_gbuf);
    cudaGetSymbolAddress(&p_s, d_sv);
    cudaGetSymbolAddress(&p_t, d_tvv);
    cudaGetSymbolAddress(&p_c1, d_c1);
    cudaGetSymbolAddress(&p_sc, d_scl);
    cudaGetSymbolAddress(&p_sh, d_shf);
    cudaGetSymbolAddress(&p_bf, g_bf);
    float* hbuf = (float*)p_h;  float* gbuf = (float*)p_g;
    float* sv = (float*)p_s;    float* tv = (float*)p_t;
    float* c1 = (float*)p_c1;
    float* scl = (float*)p_sc;  float* shf = (float*)p_sh;
    __nv_bfloat16* bf = (__nv_bfloat16*)p_bf;

    // ---- CSR build ----
    k_init_deg<<<(NN + 255) / 256, 256>>>();
    k_count<<<(E + 255) / 256, 256>>>(ei, E);
    k_blocksum<<<512, 1024>>>();
    k_scan_bsums<<<1, 512>>>();
    k_scan_final<<<512, 1024>>>();
    k_fill<<<(E + NN + 255) / 256, 256>>>(ei, E);

    // ---- GAT layer 1 (14 -> 14) ----
    k_node_linear<14, 14, 14, 16><<<(NN + 255) / 256, 256>>>(x, W1, as1, ad1, hbuf, sv, tv);
    k_gat_agg<14, 16, 16><<<(NN * 32 + 255) / 256, 256>>>(hbuf, sv, tv, b1, gbuf);

    // ---- GAT layer 2 (14 -> 32) ----
    k_node_linear<14, 16, 32, 32><<<(NN + 255) / 256, 256>>>(gbuf, W2, as2, ad2, hbuf, sv, tv);
    k_gat_agg<32, 32, 32><<<(NN * 32 + 255) / 256, 256>>>(hbuf, sv, tv, b2, gbuf);

    // ---- pool -> comb[:, 0:32] as bf16 hi/lo ----
    k_pool<<<(BB * 32 + 255) / 256, 256>>>(batch, gbuf, bf + O_CMB_H, bf + O_CMB_L);

    // ---- BN/bias fold ----
    k_prep<<<2, 256>>>(fc1_b, bn1, 400, scl + 0, shf + 0);
    k_prep<<<1, 256>>>(fc2_b, bn2, 200, scl + 400, shf + 400);
    k_prep<<<2, 256>>>(fc3_b, bn3, 400, scl + 600, shf + 600);
    k_prep<<<1, 256>>>(fc4_b, bn4, 200, scl + 1000, shf + 1000);
    k_prep<<<1, 128>>>(fcc1_b, bnc, 100, scl + 1200, shf + 1200);

    // ---- activation splits (x4 vectorized) ----
    {
        long n4 = 16384L * 1024 / 4;
        k_asplit<<<(int)((n4 + 255) / 256), 256>>>(fp, bf + O_AFP_H, bf + O_AFP_L, n4);
        n4 = 16384L * 256 / 4;
        k_asplit<<<(int)((n4 + 255) / 256), 256>>>(tvf, bf + O_ATV_H, bf + O_ATV_L, n4);
    }
    // ---- weight transpose + split + pad (rows padded to 64-multiples) ----
    k_wsplit<<<(448 * 1024 + 255) / 256, 256>>>(fc1_w, 1024, 400, 1024, 448, bf + O_W1_H, bf + O_W1_L);
    k_wsplit<<<(256 * 416 + 255) / 256, 256>>>(fc2_w, 400, 200, 416, 256, bf + O_W2_H, bf + O_W2_L);
    k_wsplit<<<(448 * 256 + 255) / 256, 256>>>(fc3_w, 256, 400, 256, 448, bf + O_W3_H, bf + O_W3_L);
    k_wsplit<<<(256 * 416 + 255) / 256, 256>>>(fc4_w, 400, 200, 416, 256, bf + O_W4_H, bf + O_W4_L);
    k_wsplit<<<(128 * 448 + 255) / 256, 256>>>(fcc1_w, 432, 100, 448, 128, bf + O_WC_H, bf + O_WC_L);

    // ---- tensor-core GEMMs (pipelined) ----
    // fc1: [16384,1024]x[1024,400] -> fp1 (pad cols 400..415 zero)
    k_mma<<<dim3(7, 128), 256, SM_TOTAL>>>(bf + O_AFP_H, bf + O_AFP_L, bf + O_W1_H, bf + O_W1_L,
                                           1024, scl + 0, shf + 0,
                                           nullptr, bf + O_FP1_H, bf + O_FP1_L, 416, 0, 400, 416);
    // fc3: [16384,256]x[256,400] -> tv1
    k_mma<<<dim3(7, 128), 256, SM_TOTAL>>>(bf + O_ATV_H, bf + O_ATV_L, bf + O_W3_H, bf + O_W3_L,
                                           256, scl + 600, shf + 600,
                                           nullptr, bf + O_TV1_H, bf + O_TV1_L, 416, 0, 400, 416);
    // fc2: [16384,416]x[416,200] -> comb[:,32:232]
    k_mma<<<dim3(4, 128), 256, SM_TOTAL>>>(bf + O_FP1_H, bf + O_FP1_L, bf + O_W2_H, bf + O_W2_L,
                                           416, scl + 400, shf + 400,
                                           nullptr, bf + O_CMB_H, bf + O_CMB_L, 448, 32, 200, 200);
    // fc4: [16384,416]x[416,200] -> comb[:,232:432], zero comb[:,432:448]
    k_mma<<<dim3(4, 128), 256, SM_TOTAL>>>(bf + O_TV1_H, bf + O_TV1_L, bf + O_W4_H, bf + O_W4_L,
                                           416, scl + 1000, shf + 1000,
                                           nullptr, bf + O_CMB_H, bf + O_CMB_L, 448, 232, 200, 216);
    // fcc1: [16384,448]x[448,100] -> c1 fp32
    k_mma<<<dim3(2, 128), 256, SM_TOTAL>>>(bf + O_CMB_H, bf + O_CMB_L, bf + O_WC_H, bf + O_WC_L,
                                           448, scl + 1200, shf + 1200,
                                           c1, nullptr, nullptr, 100, 0, 100, 100);

    k_final<<<(BB + 127) / 128, 128>>>(c1, fcc2_w, fcc2_b, out);
}

// round 7
// speedup vs baseline: 1.3136x; 1.0608x over previous
#include <cuda_runtime.h>
#include <cuda_bf16.h>
#include <cstdint>
#include <math.h>

#define NN 524288
#define EE 4194304
#define BB 16384
#define SLOPE 0.2f

// ---------------- scratch (device globals; no allocation allowed) ----------------
__device__ int   d_rowptr[NN + 1];
__device__ int   d_cursor[NN];
__device__ int   d_bsum[512];
__device__ int   d_col[EE + NN];
__device__ float d_hbuf[NN * 32];
__device__ float d_gbuf[NN * 32];
__device__ float d_sv[NN];
__device__ float d_tvv[NN];
__device__ float d_c1[BB * 100];
__device__ float d_scl[1300];
__device__ float d_shf[1300];

// bf16 split buffers; K dims padded so Kp%32==0, weight rows padded to 64-multiples
constexpr long O_AFP_H = 0;                         // fp input [16384 x 1024]
constexpr long O_AFP_L = O_AFP_H + 16384L * 1024;
constexpr long O_ATV_H = O_AFP_L + 16384L * 1024;   // tv input [16384 x 256]
constexpr long O_ATV_L = O_ATV_H + 16384L * 256;
constexpr long O_FP1_H = O_ATV_L + 16384L * 256;    // fc1 out [16384 x 448] (400 valid)
constexpr long O_FP1_L = O_FP1_H + 16384L * 448;
constexpr long O_TV1_H = O_FP1_L + 16384L * 448;    // fc3 out [16384 x 448]
constexpr long O_TV1_L = O_TV1_H + 16384L * 448;
constexpr long O_CMB_H = O_TV1_L + 16384L * 448;    // comb [16384 x 448]
constexpr long O_CMB_L = O_CMB_H + 16384L * 448;
constexpr long O_W1_H  = O_CMB_L + 16384L * 448;    // w1t [448 x 1024] (400 valid rows)
constexpr long O_W1_L  = O_W1_H + 448L * 1024;
constexpr long O_W2_H  = O_W1_L + 448L * 1024;      // w2t [256 x 448] (200 valid)
constexpr long O_W2_L  = O_W2_H + 256L * 448;
constexpr long O_W3_H  = O_W2_L + 256L * 448;       // w3t [448 x 256] (400 valid)
constexpr long O_W3_L  = O_W3_H + 448L * 256;
constexpr long O_W4_H  = O_W3_L + 448L * 256;       // w4t [256 x 448] (200 valid)
constexpr long O_W4_L  = O_W4_H + 256L * 448;
constexpr long O_WC_H  = O_W4_L + 256L * 448;       // wct [128 x 448] (100 valid)
constexpr long O_WC_L  = O_WC_H + 128L * 448;
constexpr long O_END   = O_WC_L + 128L * 448;
__device__ __nv_bfloat16 g_bf[O_END];

// ---------------- CSR build ----------------
__global__ void k_init_deg() {
    int i = blockIdx.x * blockDim.x + threadIdx.x;
    if (i < NN) d_cursor[i] = 1;
}

__global__ void k_count(const int* __restrict__ ei, int E) {
    int e = blockIdx.x * blockDim.x + threadIdx.x;
    if (e >= E) return;
    atomicAdd(&d_cursor[ei[E + e]], 1);
}

__global__ void k_blocksum() {
    __shared__ int s[1024];
    int i = blockIdx.x * 1024 + threadIdx.x;
    s[threadIdx.x] = d_cursor[i];
    __syncthreads();
    for (int o = 512; o > 0; o >>= 1) {
        if (threadIdx.x < o) s[threadIdx.x] += s[threadIdx.x + o];
        __syncthreads();
    }
    if (threadIdx.x == 0) d_bsum[blockIdx.x] = s[0];
}

__global__ void k_scan_bsums() {
    __shared__ int s[512];
    int tid = threadIdx.x;
    int v = d_bsum[tid];
    s[tid] = v;
    __syncthreads();
    for (int o = 1; o < 512; o <<= 1) {
        int t = (tid >= o) ? s[tid - o] : 0;
        __syncthreads();
        s[tid] += t;
        __syncthreads();
    }
    d_bsum[tid] = s[tid] - v;
}

__global__ void k_scan_final() {
    __shared__ int s[1024];
    int tid = threadIdx.x;
    int i = blockIdx.x * 1024 + tid;
    int v = d_cursor[i];
    s[tid] = v;
    __syncthreads();
    for (int o = 1; o < 1024; o <<= 1) {
        int t = (tid >= o) ? s[tid - o] : 0;
        __syncthreads();
        s[tid] += t;
        __syncthreads();
    }
    int ex = s[tid] - v + d_bsum[blockIdx.x];
    d_rowptr[i] = ex;
    d_cursor[i] = ex;
    if (i == NN - 1) d_rowptr[NN] = ex + v;
}

__global__ void k_fill(const int* __restrict__ ei, int E) {
    int e = blockIdx.x * blockDim.x + threadIdx.x;
    if (e >= E + NN) return;
    int src, dst;
    if (e < E) { src = ei[e]; dst = ei[E + e]; }
    else       { src = dst = e - E; }
    int pos = atomicAdd(&d_cursor[dst], 1);
    d_col[pos] = src;
}

// ---------------- node-wise linear ----------------
template <int CIN, int CINS, int COUT, int COUTS>
__global__ void k_node_linear(const float* __restrict__ X, const float* __restrict__ W,
                              const float* __restrict__ asrc, const float* __restrict__ adst,
                              float* __restrict__ H, float* __restrict__ S, float* __restrict__ T) {
    __shared__ float sW[CIN * COUT];
    __shared__ float sa[COUT], sd[COUT];
    for (int i = threadIdx.x; i < CIN * COUT; i += blockDim.x) sW[i] = W[i];
    for (int i = threadIdx.x; i < COUT; i += blockDim.x) { sa[i] = asrc[i]; sd[i] = adst[i]; }
    __syncthreads();
    int i = blockIdx.x * blockDim.x + threadIdx.x;
    if (i >= NN) return;
    float xr[CIN];
#pragma unroll
    for (int k = 0; k < CIN; k++) xr[k] = X[(long)i * CINS + k];
    float acc[COUT];
#pragma unroll
    for (int j = 0; j < COUT; j++) acc[j] = 0.f;
#pragma unroll
    for (int k = 0; k < CIN; k++) {
        float xv = xr[k];
#pragma unroll
        for (int j = 0; j < COUT; j++) acc[j] = fmaf(xv, sW[k * COUT + j], acc[j]);
    }
    float s = 0.f, t = 0.f;
#pragma unroll
    for (int j = 0; j < COUT; j++) { s = fmaf(acc[j], sa[j], s); t = fmaf(acc[j], sd[j], t); }
#pragma unroll
    for (int j = 0; j < COUTS; j++)
        H[(long)i * COUTS + j] = (j < COUT) ? acc[j] : 0.f;
    S[i] = s;
    T[i] = t;
}

// ---------------- GAT aggregation: chunk-4 batched loads + chunked online softmax ----------------
template <int C, int HS, int OUTS>
__global__ void k_gat_agg(const float* __restrict__ H, const float* __restrict__ S,
                          const float* __restrict__ T, const float* __restrict__ bias,
                          float* __restrict__ OUT) {
    int warp = (blockIdx.x * blockDim.x + threadIdx.x) >> 5;
    int lane = threadIdx.x & 31;
    if (warp >= NN) return;
    int p0 = d_rowptr[warp];
    int p1 = d_rowptr[warp + 1];
    float ti = T[warp];
    bool fl = (lane < C);
    float m = -INFINITY, sum = 0.f, acc = 0.f;
    for (int p = p0; p < p1; p += 4) {
        int n = p1 - p;
        int s0 = __ldg(&d_col[p]);
        int s1 = (n > 1) ? __ldg(&d_col[p + 1]) : 0;
        int s2 = (n > 2) ? __ldg(&d_col[p + 2]) : 0;
        int s3 = (n > 3) ? __ldg(&d_col[p + 3]) : 0;
        float e0 = S[s0] + ti;
        float e1 = (n > 1) ? S[s1] + ti : -INFINITY;
        float e2 = (n > 2) ? S[s2] + ti : -INFINITY;
        float e3 = (n > 3) ? S[s3] + ti : -INFINITY;
        float h0 = fl ? H[(long)s0 * HS + lane] : 0.f;
        float h1 = (fl && n > 1) ? H[(long)s1 * HS + lane] : 0.f;
        float h2 = (fl && n > 2) ? H[(long)s2 * HS + lane] : 0.f;
        float h3 = (fl && n > 3) ? H[(long)s3 * HS + lane] : 0.f;
        e0 = (e0 > 0.f) ? e0 : SLOPE * e0;
        e1 = (e1 > 0.f) ? e1 : SLOPE * e1;
        e2 = (e2 > 0.f) ? e2 : SLOPE * e2;
        e3 = (e3 > 0.f) ? e3 : SLOPE * e3;
        float cm = fmaxf(fmaxf(e0, e1), fmaxf(e2, e3));
        if (cm > m) {
            float sc = __expf(m - cm);
            sum *= sc;
            acc *= sc;
            m = cm;
        }
        float w0 = __expf(e0 - m);
        float w1 = __expf(e1 - m);
        float w2 = __expf(e2 - m);
        float w3 = __expf(e3 - m);
        sum += (w0 + w1) + (w2 + w3);
        acc = fmaf(w0, h0, acc);
        acc = fmaf(w1, h1, acc);
        acc = fmaf(w2, h2, acc);
        acc = fmaf(w3, h3, acc);
    }
    if (fl) {
        float v = acc / sum + bias[lane];
        OUT[(long)warp * OUTS + lane] = (v > 0.f) ? v : 0.f;
    } else if (lane < OUTS) {
        OUT[(long)warp * OUTS + lane] = 0.f;
    }
}

// ---------------- pool: warp per graph -> comb hi/lo bf16 ----------------
__global__ void k_pool(const int* __restrict__ batch, const float* __restrict__ G,
                       __nv_bfloat16* __restrict__ ch, __nv_bfloat16* __restrict__ cl) {
    int warp = (blockIdx.x * blockDim.x + threadIdx.x) >> 5;
    int lane = threadIdx.x & 31;
    if (warp >= BB) return;
    int b = warp;
    int lo = 0, hi = NN;
    while (lo < hi) { int mid = (lo + hi) >> 1; if (batch[mid] < b) lo = mid + 1; else hi = mid; }
    int start = lo;
    hi = NN;
    while (lo < hi) { int mid = (lo + hi) >> 1; if (batch[mid] < b + 1) lo = mid + 1; else hi = mid; }
    int end = lo;
    float s = 0.f;
    for (int r = start; r < end; r++) s += G[(long)r * 32 + lane];
    __nv_bfloat16 h = __float2bfloat16(s);
    ch[(long)b * 448 + lane] = h;
    cl[(long)b * 448 + lane] = __float2bfloat16(s - __bfloat162float(h));
}

// ---------------- BN/bias fold ----------------
__global__ void k_prep(const float* __restrict__ bias, const float* __restrict__ bn, int n,
                       float* __restrict__ sc, float* __restrict__ sh) {
    int j = blockIdx.x * blockDim.x + threadIdx.x;
    if (j >= n) return;
    float g = bn[j], be = bn[n + j], mu = bn[2 * n + j], va = bn[3 * n + j];
    float s = g * rsqrtf(va + 1e-5f);
    sc[j] = s;
    sh[j] = (bias[j] - mu) * s + be;
}

// ---------------- split conversions (vectorized x4) ----------------
__global__ void k_asplit(const float* __restrict__ in, __nv_bfloat16* __restrict__ h,
                         __nv_bfloat16* __restrict__ l, long n4) {
    long i = (long)blockIdx.x * blockDim.x + threadIdx.x;
    if (i >= n4) return;
    float4 v = *reinterpret_cast<const float4*>(in + i * 4);
    __nv_bfloat16 h0 = __float2bfloat16(v.x), h1 = __float2bfloat16(v.y);
    __nv_bfloat16 h2 = __float2bfloat16(v.z), h3 = __float2bfloat16(v.w);
    __nv_bfloat162* hp = reinterpret_cast<__nv_bfloat162*>(h + i * 4);
    hp[0] = __nv_bfloat162(h0, h1);
    hp[1] = __nv_bfloat162(h2, h3);
    __nv_bfloat162* lp = reinterpret_cast<__nv_bfloat162*>(l + i * 4);
    lp[0] = __nv_bfloat162(__float2bfloat16(v.x - __bfloat162float(h0)),
                           __float2bfloat16(v.y - __bfloat162float(h1)));
    lp[1] = __nv_bfloat162(__float2bfloat16(v.z - __bfloat162float(h2)),
                           __float2bfloat16(v.w - __bfloat162float(h3)));
}

// weight [K][N] -> transposed split, padded to [Np][Kp] (zero beyond N/K)
__global__ void k_wsplit(const float* __restrict__ w, int K, int N, int Kp, int Np,
                         __nv_bfloat16* __restrict__ th, __nv_bfloat16* __restrict__ tl) {
    long i = (long)blockIdx.x * blockDim.x + threadIdx.x;
    if (i >= (long)Np * Kp) return;
    int n = (int)(i / Kp);
    int k = (int)(i % Kp);
    float v = (k < K && n < N) ? w[(long)k * N + n] : 0.f;
    __nv_bfloat16 hv = __float2bfloat16(v);
    th[i] = hv;
    tl[i] = __float2bfloat16(v - __bfloat162float(hv));
}

// ---------------- tensor-core GEMM (split-bf16, 3-MMA, cp.async 2-stage pipeline) ----------------
#define LDSM4(r0, r1, r2, r3, addr) \
    asm volatile("ldmatrix.sync.aligned.m8n8.x4.shared.b16 {%0,%1,%2,%3}, [%4];" \
                 : "=r"(r0), "=r"(r1), "=r"(r2), "=r"(r3) : "r"(addr))

#define MMA16816(c, a, b) \
    asm volatile("mma.sync.aligned.m16n8k16.row.col.f32.bf16.bf16.f32 " \
                 "{%0,%1,%2,%3}, {%4,%5,%6,%7}, {%8,%9}, {%0,%1,%2,%3};" \
                 : "+f"(c[0]), "+f"(c[1]), "+f"(c[2]), "+f"(c[3]) \
                 : "r"(a[0]), "r"(a[1]), "r"(a[2]), "r"(a[3]), "r"(b[0]), "r"(b[1]))

#define CPA16(d, s) asm volatile("cp.async.cg.shared.global [%0], [%1], 16;" :: "r"(d), "l"(s))
#define CP_COMMIT   asm volatile("cp.async.commit_group;")
#define CP_WAIT1    asm volatile("cp.async.wait_group 1;")
#define CP_WAIT0    asm volatile("cp.async.wait_group 0;")

// smem halves-stride 40 (80B rows): 8-row ldmatrix addresses form a perfect 32-bank partition.
// A[stage][hl][128][40] = 40960 B, then B[stage][hl][64][40] = 20480 B
#define SAW 40
#define SM_B_BASE 40960
#define SM_TOTAL  61440

// C = relu((A @ B^T) * sc + sh). A [16384 x Kp] bf16 hi/lo; B [Np x Kp] bf16 hi/lo (padded).
__global__ __launch_bounds__(256) void k_mma(
    const __nv_bfloat16* __restrict__ Ah, const __nv_bfloat16* __restrict__ Al,
    const __nv_bfloat16* __restrict__ Bh, const __nv_bfloat16* __restrict__ Bl,
    int Kp,
    const float* __restrict__ sc, const float* __restrict__ sh,
    float* __restrict__ outF, __nv_bfloat16* __restrict__ outH, __nv_bfloat16* __restrict__ outL,
    int ldc, int cofs, int Nstore, int Nzero) {
    extern __shared__ __align__(128) __nv_bfloat16 dsm[];
    uint32_t sb = (uint32_t)__cvta_generic_to_shared(dsm);
    int tid = threadIdx.x;
    int lane = tid & 31, warp = tid >> 5;
    int wm = warp >> 1, wn = warp & 1;
    int bm = blockIdx.y * 128, bn = blockIdx.x * 64;

    float acc[2][4][4];
#pragma unroll
    for (int mi = 0; mi < 2; mi++)
#pragma unroll
        for (int ni = 0; ni < 4; ni++)
#pragma unroll
            for (int r = 0; r < 4; r++) acc[mi][ni][r] = 0.f;

    int ar = tid >> 2;           // 0..63
    int ac = (tid & 3) * 8;      // 0,8,16,24

    auto issue = [&](int kt, int stg) {
        long k0 = (long)kt * 32 + ac;
#pragma unroll
        for (int hl = 0; hl < 2; hl++) {
            const __nv_bfloat16* sa = hl ? Al : Ah;
#pragma unroll
            for (int rr = 0; rr < 2; rr++) {
                int row = ar + rr * 64;
                const void* g = sa + (long)(bm + row) * Kp + k0;
                uint32_t d = sb + ((((stg * 2 + hl) * 128 + row) * SAW + ac) << 1);
                CPA16(d, g);
            }
            const __nv_bfloat16* sbp = hl ? Bl : Bh;
            const void* gb = sbp + (long)(bn + ar) * Kp + k0;
            uint32_t db = sb + SM_B_BASE + ((((stg * 2 + hl) * 64 + ar) * SAW + ac) << 1);
            CPA16(db, gb);
        }
    };

    int T = Kp >> 5;
    issue(0, 0);
    CP_COMMIT;
    int stg = 0;
    for (int kt = 0; kt < T; kt++) {
        if (kt + 1 < T) {
            issue(kt + 1, stg ^ 1);
            CP_COMMIT;
            CP_WAIT1;
        } else {
            CP_WAIT0;
        }
        __syncthreads();
#pragma unroll
        for (int ks = 0; ks < 2; ks++) {
            uint32_t ah[2][4], al[2][4], bh[4][2], bl[4][2];
#pragma unroll
            for (int mi = 0; mi < 2; mi++) {
                int row = wm * 32 + mi * 16 + (lane & 15);
                int col = ks * 16 + (lane >> 4) * 8;
                uint32_t ad = sb + ((((stg * 2 + 0) * 128 + row) * SAW + col) << 1);
                LDSM4(ah[mi][0], ah[mi][1], ah[mi][2], ah[mi][3], ad);
                ad = sb + ((((stg * 2 + 1) * 128 + row) * SAW + col) << 1);
                LDSM4(al[mi][0], al[mi][1], al[mi][2], al[mi][3], ad);
            }
#pragma unroll
            for (int nh = 0; nh < 2; nh++) {
                int p = lane >> 3, l7 = lane & 7;
                int nrow = wn * 32 + nh * 16 + (p >> 1) * 8 + l7;
                int col = ks * 16 + (p & 1) * 8;
                uint32_t ad = sb + SM_B_BASE + ((((stg * 2 + 0) * 64 + nrow) * SAW + col) << 1);
                LDSM4(bh[2 * nh][0], bh[2 * nh][1], bh[2 * nh + 1][0], bh[2 * nh + 1][1], ad);
                ad = sb + SM_B_BASE + ((((stg * 2 + 1) * 64 + nrow) * SAW + col) << 1);
                LDSM4(bl[2 * nh][0], bl[2 * nh][1], bl[2 * nh + 1][0], bl[2 * nh + 1][1], ad);
            }
#pragma unroll
            for (int mi = 0; mi < 2; mi++)
#pragma unroll
                for (int ni = 0; ni < 4; ni++) {
                    MMA16816(acc[mi][ni], ah[mi], bh[ni]);
                    MMA16816(acc[mi][ni], ah[mi], bl[ni]);
                    MMA16816(acc[mi][ni], al[mi], bh[ni]);
                }
        }
        __syncthreads();
        stg ^= 1;
    }

    // epilogue: scale/shift + relu, write fp32 and/or bf16 hi/lo
    int g = lane >> 2, t2 = (lane & 3) * 2;
#pragma unroll
    for (int mi = 0; mi < 2; mi++)
#pragma unroll
        for (int ni = 0; ni < 4; ni++)
#pragma unroll
            for (int r = 0; r < 4; r++) {
                int gm = bm + wm * 32 + mi * 16 + g + ((r >> 1) * 8);
                int gn = bn + wn * 32 + ni * 8 + t2 + (r & 1);
                if (gn < Nzero) {
                    float val = 0.f;
                    if (gn < Nstore) {
                        val = acc[mi][ni][r] * sc[gn] + sh[gn];
                        val = (val > 0.f) ? val : 0.f;
                    }
                    long o = (long)gm * ldc + cofs + gn;
                    if (outF) outF[o] = val;
                    if (outH) {
                        __nv_bfloat16 hv = __float2bfloat16(val);
                        outH[o] = hv;
                        outL[o] = __float2bfloat16(val - __bfloat162float(hv));
                    }
                }
            }
}

// ---------------- final fc ----------------
__global__ void k_final(const float* __restrict__ Cc, const float* __restrict__ w,
                        const float* __restrict__ b, float* __restrict__ out) {
    int m = blockIdx.x * blockDim.x + threadIdx.x;
    if (m >= BB) return;
    float s = b[0];
#pragma unroll 4
    for (int j = 0; j < 100; j++) s = fmaf(Cc[(long)m * 100 + j], w[j], s);
    out[m] = s;
}

// ---------------- launch ----------------
extern "C" void kernel_launch(void* const* d_in, const int* in_sizes, int n_in,
                              void* d_out, int out_size) {
    const float* x      = (const float*)d_in[0];
    const int*   ei     = (const int*)d_in[1];
    const int*   batch  = (const int*)d_in[2];
    const float* fp     = (const float*)d_in[3];
    const float* tvf    = (const float*)d_in[4];
    const float* W1     = (const float*)d_in[5];
    const float* as1    = (const float*)d_in[6];
    const float* ad1    = (const float*)d_in[7];
    const float* b1     = (const float*)d_in[8];
    const float* W2     = (const float*)d_in[9];
    const float* as2    = (const float*)d_in[10];
    const float* ad2    = (const float*)d_in[11];
    const float* b2     = (const float*)d_in[12];
    const float* fc1_w  = (const float*)d_in[13];
    const float* fc1_b  = (const float*)d_in[14];
    const float* bn1    = (const float*)d_in[15];
    const float* fc2_w  = (const float*)d_in[16];
    const float* fc2_b  = (const float*)d_in[17];
    const float* bn2    = (const float*)d_in[18];
    const float* fc3_w  = (const float*)d_in[19];
    const float* fc3_b  = (const float*)d_in[20];
    const float* bn3    = (const float*)d_in[21];
    const float* fc4_w  = (const float*)d_in[22];
    const float* fc4_b  = (const float*)d_in[23];
    const float* bn4    = (const float*)d_in[24];
    const float* fcc1_w = (const float*)d_in[25];
    const float* fcc1_b = (const float*)d_in[26];
    const float* bnc    = (const float*)d_in[27];
    const float* fcc2_w = (const float*)d_in[28];
    const float* fcc2_b = (const float*)d_in[29];
    float* out = (float*)d_out;

    int E = in_sizes[1] / 2;

    static int inited = 0;
    static cudaStream_t sB = 0;
    static cudaEvent_t evF = 0, evJ = 0;
    if (!inited) {
        cudaFuncSetAttribute(k_mma, cudaFuncAttributeMaxDynamicSharedMemorySize, SM_TOTAL);
        cudaStreamCreateWithFlags(&sB, cudaStreamNonBlocking);
        cudaEventCreateWithFlags(&evF, cudaEventDisableTiming);
        cudaEventCreateWithFlags(&evJ, cudaEventDisableTiming);
        inited = 1;
    }

    void *p_h, *p_g, *p_s, *p_t, *p_c1, *p_sc, *p_sh, *p_bf;
    cudaGetSymbolAddress(&p_h, d_hbuf);
    cudaGetSymbolAddress(&p_g, d_gbuf);
    cudaGetSymbolAddress(&p_s, d_sv);
    cudaGetSymbolAddress(&p_t, d_tvv);
    cudaGetSymbolAddress(&p_c1, d_c1);
    cudaGetSymbolAddress(&p_sc, d_scl);
    cudaGetSymbolAddress(&p_sh, d_shf);
    cudaGetSymbolAddress(&p_bf, g_bf);
    float* hbuf = (float*)p_h;  float* gbuf = (float*)p_g;
    float* sv = (float*)p_s;    float* tv = (float*)p_t;
    float* c1 = (float*)p_c1;
    float* scl = (float*)p_sc;  float* shf = (float*)p_sh;
    __nv_bfloat16* bf = (__nv_bfloat16*)p_bf;

    // fork: graph branch runs on sB concurrently with dense branch on stream 0
    cudaEventRecord(evF, 0);
    cudaStreamWaitEvent(sB, evF, 0);

    // ---- dense branch prologue (stream 0); fc1 GEMM is launch index 5 for ncu ----
    {
        long n4 = 16384L * 1024 / 4;
        k_asplit<<<(int)((n4 + 255) / 256), 256>>>(fp, bf + O_AFP_H, bf + O_AFP_L, n4);
    }
    k_wsplit<<<(448 * 1024 + 255) / 256, 256>>>(fc1_w, 1024, 400, 1024, 448, bf + O_W1_H, bf + O_W1_L);
    k_prep<<<2, 256>>>(fc1_b, bn1, 400, scl + 0, shf + 0);
    {
        long n4 = 16384L * 256 / 4;
        k_asplit<<<(int)((n4 + 255) / 256), 256>>>(tvf, bf + O_ATV_H, bf + O_ATV_L, n4);
    }
    k_wsplit<<<(448 * 256 + 255) / 256, 256>>>(fc3_w, 256, 400, 256, 448, bf + O_W3_H, bf + O_W3_L);
    // fc1: [16384,1024]x[1024,400] -> fp1 [16384 x 448]
    k_mma<<<dim3(7, 128), 256, SM_TOTAL>>>(bf + O_AFP_H, bf + O_AFP_L, bf + O_W1_H, bf + O_W1_L,
                                           1024, scl + 0, shf + 0,
                                           nullptr, bf + O_FP1_H, bf + O_FP1_L, 448, 0, 400, 448);

    // ---- graph branch (stream sB): CSR + GAT x2 + pool ----
    k_init_deg<<<(NN + 255) / 256, 256, 0, sB>>>();
    k_count<<<(E + 255) / 256, 256, 0, sB>>>(ei, E);
    k_blocksum<<<512, 1024, 0, sB>>>();
    k_scan_bsums<<<1, 512, 0, sB>>>();
    k_scan_final<<<512, 1024, 0, sB>>>();
    k_fill<<<(E + NN + 255) / 256, 256, 0, sB>>>(ei, E);
    k_node_linear<14, 14, 14, 16><<<(NN + 255) / 256, 256, 0, sB>>>(x, W1, as1, ad1, hbuf, sv, tv);
    k_gat_agg<14, 16, 16><<<(NN * 32 + 255) / 256, 256, 0, sB>>>(hbuf, sv, tv, b1, gbuf);
    k_node_linear<14, 16, 32, 32><<<(NN + 255) / 256, 256, 0, sB>>>(gbuf, W2, as2, ad2, hbuf, sv, tv);
    k_gat_agg<32, 32, 32><<<(NN * 32 + 255) / 256, 256, 0, sB>>>(hbuf, sv, tv, b2, gbuf);
    k_pool<<<(BB * 32 + 255) / 256, 256, 0, sB>>>(batch, gbuf, bf + O_CMB_H, bf + O_CMB_L);

    // ---- dense branch continues (stream 0) ----
    k_prep<<<2, 256>>>(fc3_b, bn3, 400, scl + 600, shf + 600);
    // fc3: [16384,256]x[256,400] -> tv1
    k_mma<<<dim3(7, 128), 256, SM_TOTAL>>>(bf + O_ATV_H, bf + O_ATV_L, bf + O_W3_H, bf + O_W3_L,
                                           256, scl + 600, shf + 600,
                                           nullptr, bf + O_TV1_H, bf + O_TV1_L, 448, 0, 400, 448);
    k_wsplit<<<(256 * 448 + 255) / 256, 256>>>(fc2_w, 400, 200, 448, 256, bf + O_W2_H, bf + O_W2_L);
    k_prep<<<1, 256>>>(fc2_b, bn2, 200, scl + 400, shf + 400);
    // fc2: [16384,448]x[448,200] -> comb[:,32:232]
    k_mma<<<dim3(4, 128), 256, SM_TOTAL>>>(bf + O_FP1_H, bf + O_FP1_L, bf + O_W2_H, bf + O_W2_L,
                                           448, scl + 400, shf + 400,
                                           nullptr, bf + O_CMB_H, bf + O_CMB_L, 448, 32, 200, 200);
    k_wsplit<<<(256 * 448 + 255) / 256, 256>>>(fc4_w, 400, 200, 448, 256, bf + O_W4_H, bf + O_W4_L);
    k_prep<<<1, 256>>>(fc4_b, bn4, 200, scl + 1000, shf + 1000);
    // fc4: [16384,448]x[448,200] -> comb[:,232:432], zero comb[:,432:448]
    k_mma<<<dim3(4, 128), 256, SM_TOTAL>>>(bf + O_TV1_H, bf + O_TV1_L, bf + O_W4_H, bf + O_W4_L,
                                           448, scl + 1000, shf + 1000,
                                           nullptr, bf + O_CMB_H, bf + O_CMB_L, 448, 232, 200, 216);
    k_wsplit<<<(128 * 448 + 255) / 256, 256>>>(fcc1_w, 432, 100, 448, 128, bf + O_WC_H, bf + O_WC_L);
    k_prep<<<1, 128>>>(fcc1_b, bnc, 100, scl + 1200, shf + 1200);

    // join: fcc1 needs comb (pool on sB + fc2/fc4 on 0)
    cudaEventRecord(evJ, sB);
    cudaStreamWaitEvent(0, evJ, 0);

    // fcc1: [16384,448]x[448,100] -> c1 fp32
    k_mma<<<dim3(2, 128), 256, SM_TOTAL>>>(bf + O_CMB_H, bf + O_CMB_L, bf + O_WC_H, bf + O_WC_L,
                                           448, scl + 1200, shf + 1200,
                                           c1, nullptr, nullptr, 100, 0, 100, 100);
    k_final<<<(BB + 127) / 128, 128>>>(c1, fcc2_w, fcc2_b, out);
}

// round 8
// speedup vs baseline: 1.5117x; 1.1508x over previous
#include <cuda_runtime.h>
#include <cuda_fp16.h>
#include <cstdint>
#include <math.h>

#define NN 524288
#define EE 4194304
#define BB 16384
#define SLOPE 0.2f

// ---------------- scratch (device globals; no allocation allowed) ----------------
__device__ int   d_rowptr[NN + 1];
__device__ int   d_cursor[NN];
__device__ int   d_bsum[512];
__device__ int   d_col[EE + NN];
__device__ float d_hbuf[NN * 32];
__device__ float d_gbuf[NN * 32];
__device__ float d_sv[NN];
__device__ float d_tvv[NN];
__device__ float d_c1[BB * 100];
__device__ float d_scl[1300];
__device__ float d_shf[1300];

// fp16 buffers: activations hi-only; weights hi+lo. K dims %32==0, weight rows padded to 64.
constexpr long O_AFP  = 0;                          // fp input [16384 x 1024]
constexpr long O_ATV  = O_AFP + 16384L * 1024;      // tv input [16384 x 256]
constexpr long O_FP1  = O_ATV + 16384L * 256;       // fc1 out [16384 x 448] (400 valid)
constexpr long O_TV1  = O_FP1 + 16384L * 448;       // fc3 out [16384 x 448]
constexpr long O_CMB  = O_TV1 + 16384L * 448;       // comb [16384 x 448]
constexpr long O_W1_H = O_CMB + 16384L * 448;       // w1t [448 x 1024] (400 valid rows)
constexpr long O_W1_L = O_W1_H + 448L * 1024;
constexpr long O_W2_H = O_W1_L + 448L * 1024;       // w2t [256 x 448] (200 valid)
constexpr long O_W2_L = O_W2_H + 256L * 448;
constexpr long O_W3_H = O_W2_L + 256L * 448;        // w3t [448 x 256] (400 valid)
constexpr long O_W3_L = O_W3_H + 448L * 256;
constexpr long O_W4_H = O_W3_L + 448L * 256;        // w4t [256 x 448] (200 valid)
constexpr long O_W4_L = O_W4_H + 256L * 448;
constexpr long O_WC_H = O_W4_L + 256L * 448;        // wct [128 x 448] (100 valid)
constexpr long O_WC_L = O_WC_H + 128L * 448;
constexpr long O_END  = O_WC_L + 128L * 448;
__device__ __half g_hf[O_END];

// ---------------- CSR build ----------------
__global__ void k_init_deg() {
    int i = blockIdx.x * blockDim.x + threadIdx.x;
    if (i < NN) d_cursor[i] = 1;
}

__global__ void k_count(const int* __restrict__ ei, int E) {
    int e = blockIdx.x * blockDim.x + threadIdx.x;
    if (e >= E) return;
    atomicAdd(&d_cursor[ei[E + e]], 1);
}

__global__ void k_blocksum() {
    __shared__ int s[1024];
    int i = blockIdx.x * 1024 + threadIdx.x;
    s[threadIdx.x] = d_cursor[i];
    __syncthreads();
    for (int o = 512; o > 0; o >>= 1) {
        if (threadIdx.x < o) s[threadIdx.x] += s[threadIdx.x + o];
        __syncthreads();
    }
    if (threadIdx.x == 0) d_bsum[blockIdx.x] = s[0];
}

__global__ void k_scan_bsums() {
    __shared__ int s[512];
    int tid = threadIdx.x;
    int v = d_bsum[tid];
    s[tid] = v;
    __syncthreads();
    for (int o = 1; o < 512; o <<= 1) {
        int t = (tid >= o) ? s[tid - o] : 0;
        __syncthreads();
        s[tid] += t;
        __syncthreads();
    }
    d_bsum[tid] = s[tid] - v;
}

__global__ void k_scan_final() {
    __shared__ int s[1024];
    int tid = threadIdx.x;
    int i = blockIdx.x * 1024 + tid;
    int v = d_cursor[i];
    s[tid] = v;
    __syncthreads();
    for (int o = 1; o < 1024; o <<= 1) {
        int t = (tid >= o) ? s[tid - o] : 0;
        __syncthreads();
        s[tid] += t;
        __syncthreads();
    }
    int ex = s[tid] - v + d_bsum[blockIdx.x];
    d_rowptr[i] = ex;
    d_cursor[i] = ex;
    if (i == NN - 1) d_rowptr[NN] = ex + v;
}

__global__ void k_fill(const int* __restrict__ ei, int E) {
    int e = blockIdx.x * blockDim.x + threadIdx.x;
    if (e >= E + NN) return;
    int src, dst;
    if (e < E) { src = ei[e]; dst = ei[E + e]; }
    else       { src = dst = e - E; }
    int pos = atomicAdd(&d_cursor[dst], 1);
    d_col[pos] = src;
}

// ---------------- node-wise linear ----------------
template <int CIN, int CINS, int COUT, int COUTS>
__global__ void k_node_linear(const float* __restrict__ X, const float* __restrict__ W,
                              const float* __restrict__ asrc, const float* __restrict__ adst,
                              float* __restrict__ H, float* __restrict__ S, float* __restrict__ T) {
    __shared__ float sW[CIN * COUT];
    __shared__ float sa[COUT], sd[COUT];
    for (int i = threadIdx.x; i < CIN * COUT; i += blockDim.x) sW[i] = W[i];
    for (int i = threadIdx.x; i < COUT; i += blockDim.x) { sa[i] = asrc[i]; sd[i] = adst[i]; }
    __syncthreads();
    int i = blockIdx.x * blockDim.x + threadIdx.x;
    if (i >= NN) return;
    float xr[CIN];
#pragma unroll
    for (int k = 0; k < CIN; k++) xr[k] = X[(long)i * CINS + k];
    float acc[COUT];
#pragma unroll
    for (int j = 0; j < COUT; j++) acc[j] = 0.f;
#pragma unroll
    for (int k = 0; k < CIN; k++) {
        float xv = xr[k];
#pragma unroll
        for (int j = 0; j < COUT; j++) acc[j] = fmaf(xv, sW[k * COUT + j], acc[j]);
    }
    float s = 0.f, t = 0.f;
#pragma unroll
    for (int j = 0; j < COUT; j++) { s = fmaf(acc[j], sa[j], s); t = fmaf(acc[j], sd[j], t); }
#pragma unroll
    for (int j = 0; j < COUTS; j++)
        H[(long)i * COUTS + j] = (j < COUT) ? acc[j] : 0.f;
    S[i] = s;
    T[i] = t;
}

// ---------------- GAT aggregation: chunk-4 batched loads + chunked online softmax ----------------
template <int C, int HS, int OUTS>
__global__ void k_gat_agg(const float* __restrict__ H, const float* __restrict__ S,
                          const float* __restrict__ T, const float* __restrict__ bias,
                          float* __restrict__ OUT) {
    int warp = (blockIdx.x * blockDim.x + threadIdx.x) >> 5;
    int lane = threadIdx.x & 31;
    if (warp >= NN) return;
    int p0 = d_rowptr[warp];
    int p1 = d_rowptr[warp + 1];
    float ti = T[warp];
    bool fl = (lane < C);
    float m = -INFINITY, sum = 0.f, acc = 0.f;
    for (int p = p0; p < p1; p += 4) {
        int n = p1 - p;
        int s0 = __ldg(&d_col[p]);
        int s1 = (n > 1) ? __ldg(&d_col[p + 1]) : 0;
        int s2 = (n > 2) ? __ldg(&d_col[p + 2]) : 0;
        int s3 = (n > 3) ? __ldg(&d_col[p + 3]) : 0;
        float e0 = S[s0] + ti;
        float e1 = (n > 1) ? S[s1] + ti : -INFINITY;
        float e2 = (n > 2) ? S[s2] + ti : -INFINITY;
        float e3 = (n > 3) ? S[s3] + ti : -INFINITY;
        float h0 = fl ? H[(long)s0 * HS + lane] : 0.f;
        float h1 = (fl && n > 1) ? H[(long)s1 * HS + lane] : 0.f;
        float h2 = (fl && n > 2) ? H[(long)s2 * HS + lane] : 0.f;
        float h3 = (fl && n > 3) ? H[(long)s3 * HS + lane] : 0.f;
        e0 = (e0 > 0.f) ? e0 : SLOPE * e0;
        e1 = (e1 > 0.f) ? e1 : SLOPE * e1;
        e2 = (e2 > 0.f) ? e2 : SLOPE * e2;
        e3 = (e3 > 0.f) ? e3 : SLOPE * e3;
        float cm = fmaxf(fmaxf(e0, e1), fmaxf(e2, e3));
        if (cm > m) {
            float sc = __expf(m - cm);
            sum *= sc;
            acc *= sc;
            m = cm;
        }
        float w0 = __expf(e0 - m);
        float w1 = __expf(e1 - m);
        float w2 = __expf(e2 - m);
        float w3 = __expf(e3 - m);
        sum += (w0 + w1) + (w2 + w3);
        acc = fmaf(w0, h0, acc);
        acc = fmaf(w1, h1, acc);
        acc = fmaf(w2, h2, acc);
        acc = fmaf(w3, h3, acc);
    }
    if (fl) {
        float v = acc / sum + bias[lane];
        OUT[(long)warp * OUTS + lane] = (v > 0.f) ? v : 0.f;
    } else if (lane < OUTS) {
        OUT[(long)warp * OUTS + lane] = 0.f;
    }
}

// ---------------- pool: warp per graph -> comb fp16 ----------------
__global__ void k_pool(const int* __restrict__ batch, const float* __restrict__ G,
                       __half* __restrict__ ch) {
    int warp = (blockIdx.x * blockDim.x + threadIdx.x) >> 5;
    int lane = threadIdx.x & 31;
    if (warp >= BB) return;
    int b = warp;
    int lo = 0, hi = NN;
    while (lo < hi) { int mid = (lo + hi) >> 1; if (batch[mid] < b) lo = mid + 1; else hi = mid; }
    int start = lo;
    hi = NN;
    while (lo < hi) { int mid = (lo + hi) >> 1; if (batch[mid] < b + 1) lo = mid + 1; else hi = mid; }
    int end = lo;
    float s = 0.f;
    for (int r = start; r < end; r++) s += G[(long)r * 32 + lane];
    ch[(long)b * 448 + lane] = __float2half(s);
}

// ---------------- BN/bias fold ----------------
__global__ void k_prep(const float* __restrict__ bias, const float* __restrict__ bn, int n,
                       float* __restrict__ sc, float* __restrict__ sh) {
    int j = blockIdx.x * blockDim.x + threadIdx.x;
    if (j >= n) return;
    float g = bn[j], be = bn[n + j], mu = bn[2 * n + j], va = bn[3 * n + j];
    float s = g * rsqrtf(va + 1e-5f);
    sc[j] = s;
    sh[j] = (bias[j] - mu) * s + be;
}

// ---------------- activation fp32 -> fp16 (hi only, x4 vectorized) ----------------
__global__ void k_ahalf(const float* __restrict__ in, __half* __restrict__ h, long n4) {
    long i = (long)blockIdx.x * blockDim.x + threadIdx.x;
    if (i >= n4) return;
    float4 v = *reinterpret_cast<const float4*>(in + i * 4);
    __half2* hp = reinterpret_cast<__half2*>(h + i * 4);
    hp[0] = __floats2half2_rn(v.x, v.y);
    hp[1] = __floats2half2_rn(v.z, v.w);
}

// weight [K][N] -> transposed fp16 hi/lo split, padded to [Np][Kp]
__global__ void k_whalf(const float* __restrict__ w, int K, int N, int Kp, int Np,
                        __half* __restrict__ th, __half* __restrict__ tl) {
    long i = (long)blockIdx.x * blockDim.x + threadIdx.x;
    if (i >= (long)Np * Kp) return;
    int n = (int)(i / Kp);
    int k = (int)(i % Kp);
    float v = (k < K && n < N) ? w[(long)k * N + n] : 0.f;
    __half hv = __float2half(v);
    th[i] = hv;
    tl[i] = __float2half(v - __half2float(hv));
}

// ---------------- tensor-core GEMM (fp16, 2-MMA: Ah*(Bh+Bl), cp.async 2-stage) ----------------
#define LDSM4(r0, r1, r2, r3, addr) \
    asm volatile("ldmatrix.sync.aligned.m8n8.x4.shared.b16 {%0,%1,%2,%3}, [%4];" \
                 : "=r"(r0), "=r"(r1), "=r"(r2), "=r"(r3) : "r"(addr))

#define MMA16816(c, a, b) \
    asm volatile("mma.sync.aligned.m16n8k16.row.col.f32.f16.f16.f32 " \
                 "{%0,%1,%2,%3}, {%4,%5,%6,%7}, {%8,%9}, {%0,%1,%2,%3};" \
                 : "+f"(c[0]), "+f"(c[1]), "+f"(c[2]), "+f"(c[3]) \
                 : "r"(a[0]), "r"(a[1]), "r"(a[2]), "r"(a[3]), "r"(b[0]), "r"(b[1]))

#define CPA16(d, s) asm volatile("cp.async.cg.shared.global [%0], [%1], 16;" :: "r"(d), "l"(s))
#define CP_COMMIT   asm volatile("cp.async.commit_group;")
#define CP_WAIT1    asm volatile("cp.async.wait_group 1;")
#define CP_WAIT0    asm volatile("cp.async.wait_group 0;")

// smem halves-stride 40 (80B rows): conflict-free 8-row ldmatrix.
// stage: A[128][40] = 10240 B | Bh[64][40] = 5120 | Bl[64][40] = 5120 -> 20480 B; 2 stages.
#define SAW 40
#define SM_STG   20480
#define SM_BH    10240
#define SM_BL    15360
#define SM_TOTAL 40960

// C = relu((A @ (Bh+Bl)^T) * sc + sh). A [16384 x Kp] fp16; B [Np x Kp] fp16 hi/lo.
__global__ __launch_bounds__(256) void k_mma(
    const __half* __restrict__ Ah,
    const __half* __restrict__ Bh, const __half* __restrict__ Bl,
    int Kp,
    const float* __restrict__ sc, const float* __restrict__ sh,
    float* __restrict__ outF, __half* __restrict__ outH,
    int ldc, int cofs, int Nstore, int Nzero) {
    extern __shared__ __align__(128) __half dsm[];
    uint32_t sb = (uint32_t)__cvta_generic_to_shared(dsm);
    int tid = threadIdx.x;
    int lane = tid & 31, warp = tid >> 5;
    int wm = warp >> 1, wn = warp & 1;
    int bm = blockIdx.y * 128, bn = blockIdx.x * 64;

    float acc[2][4][4];
#pragma unroll
    for (int mi = 0; mi < 2; mi++)
#pragma unroll
        for (int ni = 0; ni < 4; ni++)
#pragma unroll
            for (int r = 0; r < 4; r++) acc[mi][ni][r] = 0.f;

    int ar = tid >> 2;           // 0..63
    int ac = (tid & 3) * 8;      // 0,8,16,24

    auto issue = [&](int kt, int stg) {
        long k0 = (long)kt * 32 + ac;
        uint32_t base = sb + stg * SM_STG;
#pragma unroll
        for (int rr = 0; rr < 2; rr++) {
            int row = ar + rr * 64;
            CPA16(base + ((row * SAW + ac) << 1), Ah + (long)(bm + row) * Kp + k0);
        }
        CPA16(base + SM_BH + ((ar * SAW + ac) << 1), Bh + (long)(bn + ar) * Kp + k0);
        CPA16(base + SM_BL + ((ar * SAW + ac) << 1), Bl + (long)(bn + ar) * Kp + k0);
    };

    int T = Kp >> 5;
    issue(0, 0);
    CP_COMMIT;
    int stg = 0;
    for (int kt = 0; kt < T; kt++) {
        if (kt + 1 < T) {
            issue(kt + 1, stg ^ 1);
            CP_COMMIT;
            CP_WAIT1;
        } else {
            CP_WAIT0;
        }
        __syncthreads();
        uint32_t base = sb + stg * SM_STG;
#pragma unroll
        for (int ks = 0; ks < 2; ks++) {
            uint32_t a_[2][4], bh_[4][2], bl_[4][2];
#pragma unroll
            for (int mi = 0; mi < 2; mi++) {
                int row = wm * 32 + mi * 16 + (lane & 15);
                int col = ks * 16 + (lane >> 4) * 8;
                uint32_t ad = base + ((row * SAW + col) << 1);
                LDSM4(a_[mi][0], a_[mi][1], a_[mi][2], a_[mi][3], ad);
            }
#pragma unroll
            for (int nh = 0; nh < 2; nh++) {
                int p = lane >> 3, l7 = lane & 7;
                int nrow = wn * 32 + nh * 16 + (p >> 1) * 8 + l7;
                int col = ks * 16 + (p & 1) * 8;
                uint32_t ad = base + SM_BH + ((nrow * SAW + col) << 1);
                LDSM4(bh_[2 * nh][0], bh_[2 * nh][1], bh_[2 * nh + 1][0], bh_[2 * nh + 1][1], ad);
                ad = base + SM_BL + ((nrow * SAW + col) << 1);
                LDSM4(bl_[2 * nh][0], bl_[2 * nh][1], bl_[2 * nh + 1][0], bl_[2 * nh + 1][1], ad);
            }
#pragma unroll
            for (int mi = 0; mi < 2; mi++)
#pragma unroll
                for (int ni = 0; ni < 4; ni++) {
                    MMA16816(acc[mi][ni], a_[mi], bh_[ni]);
                    MMA16816(acc[mi][ni], a_[mi], bl_[ni]);
                }
        }
        __syncthreads();
        stg ^= 1;
    }

    // epilogue: scale/shift + relu, write fp32 or fp16
    int g = lane >> 2, t2 = (lane & 3) * 2;
#pragma unroll
    for (int mi = 0; mi < 2; mi++)
#pragma unroll
        for (int ni = 0; ni < 4; ni++)
#pragma unroll
            for (int r = 0; r < 4; r++) {
                int gm = bm + wm * 32 + mi * 16 + g + ((r >> 1) * 8);
                int gn = bn + wn * 32 + ni * 8 + t2 + (r & 1);
                if (gn < Nzero) {
                    float val = 0.f;
                    if (gn < Nstore) {
                        val = acc[mi][ni][r] * sc[gn] + sh[gn];
                        val = (val > 0.f) ? val : 0.f;
                    }
                    long o = (long)gm * ldc + cofs + gn;
                    if (outF) outF[o] = val;
                    else      outH[o] = __float2half(val);
                }
            }
}

// ---------------- final fc ----------------
__global__ void k_final(const float* __restrict__ Cc, const float* __restrict__ w,
                        const float* __restrict__ b, float* __restrict__ out) {
    int m = blockIdx.x * blockDim.x + threadIdx.x;
    if (m >= BB) return;
    float s = b[0];
#pragma unroll 4
    for (int j = 0; j < 100; j++) s = fmaf(Cc[(long)m * 100 + j], w[j], s);
    out[m] = s;
}

// ---------------- launch ----------------
extern "C" void kernel_launch(void* const* d_in, const int* in_sizes, int n_in,
                              void* d_out, int out_size) {
    const float* x      = (const float*)d_in[0];
    const int*   ei     = (const int*)d_in[1];
    const int*   batch  = (const int*)d_in[2];
    const float* fp     = (const float*)d_in[3];
    const float* tvf    = (const float*)d_in[4];
    const float* W1     = (const float*)d_in[5];
    const float* as1    = (const float*)d_in[6];
    const float* ad1    = (const float*)d_in[7];
    const float* b1     = (const float*)d_in[8];
    const float* W2     = (const float*)d_in[9];
    const float* as2    = (const float*)d_in[10];
    const float* ad2    = (const float*)d_in[11];
    const float* b2     = (const float*)d_in[12];
    const float* fc1_w  = (const float*)d_in[13];
    const float* fc1_b  = (const float*)d_in[14];
    const float* bn1    = (const float*)d_in[15];
    const float* fc2_w  = (const float*)d_in[16];
    const float* fc2_b  = (const float*)d_in[17];
    const float* bn2    = (const float*)d_in[18];
    const float* fc3_w  = (const float*)d_in[19];
    const float* fc3_b  = (const float*)d_in[20];
    const float* bn3    = (const float*)d_in[21];
    const float* fc4_w  = (const float*)d_in[22];
    const float* fc4_b  = (const float*)d_in[23];
    const float* bn4    = (const float*)d_in[24];
    const float* fcc1_w = (const float*)d_in[25];
    const float* fcc1_b = (const float*)d_in[26];
    const float* bnc    = (const float*)d_in[27];
    const float* fcc2_w = (const float*)d_in[28];
    const float* fcc2_b = (const float*)d_in[29];
    float* out = (float*)d_out;

    int E = in_sizes[1] / 2;

    static int inited = 0;
    static cudaStream_t sB = 0;
    static cudaEvent_t evF = 0, evJ = 0;
    if (!inited) {
        cudaFuncSetAttribute(k_mma, cudaFuncAttributeMaxDynamicSharedMemorySize, SM_TOTAL);
        cudaStreamCreateWithFlags(&sB, cudaStreamNonBlocking);
        cudaEventCreateWithFlags(&evF, cudaEventDisableTiming);
        cudaEventCreateWithFlags(&evJ, cudaEventDisableTiming);
        inited = 1;
    }

    void *p_h, *p_g, *p_s, *p_t, *p_c1, *p_sc, *p_sh, *p_hf;
    cudaGetSymbolAddress(&p_h, d_hbuf);
    cudaGetSymbolAddress(&p_g, d_gbuf);
    cudaGetSymbolAddress(&p_s, d_sv);
    cudaGetSymbolAddress(&p_t, d_tvv);
    cudaGetSymbolAddress(&p_c1, d_c1);
    cudaGetSymbolAddress(&p_sc, d_scl);
    cudaGetSymbolAddress(&p_sh, d_shf);
    cudaGetSymbolAddress(&p_hf, g_hf);
    float* hbuf = (float*)p_h;  float* gbuf = (float*)p_g;
    float* sv = (float*)p_s;    float* tv = (float*)p_t;
    float* c1 = (float*)p_c1;
    float* scl = (float*)p_sc;  float* shf = (float*)p_sh;
    __half* hf = (__half*)p_hf;

    // fork: graph branch on sB, dense branch on stream 0
    cudaEventRecord(evF, 0);
    cudaStreamWaitEvent(sB, evF, 0);

    // ---- dense branch prologue (stream 0) ----
    {
        long n4 = 16384L * 1024 / 4;
        k_ahalf<<<(int)((n4 + 255) / 256), 256>>>(fp, hf + O_AFP, n4);
    }
    k_whalf<<<(448 * 1024 + 255) / 256, 256>>>(fc1_w, 1024, 400, 1024, 448, hf + O_W1_H, hf + O_W1_L);
    k_prep<<<2, 256>>>(fc1_b, bn1, 400, scl + 0, shf + 0);
    {
        long n4 = 16384L * 256 / 4;
        k_ahalf<<<(int)((n4 + 255) / 256), 256>>>(tvf, hf + O_ATV, n4);
    }
    k_whalf<<<(448 * 256 + 255) / 256, 256>>>(fc3_w, 256, 400, 256, 448, hf + O_W3_H, hf + O_W3_L);
    // fc1: [16384,1024]x[1024,400] -> fp1 [16384 x 448]
    k_mma<<<dim3(7, 128), 256, SM_TOTAL>>>(hf + O_AFP, hf + O_W1_H, hf + O_W1_L,
                                           1024, scl + 0, shf + 0,
                                           nullptr, hf + O_FP1, 448, 0, 400, 448);

    // ---- graph branch (stream sB): CSR + GAT x2 + pool ----
    k_init_deg<<<(NN + 255) / 256, 256, 0, sB>>>();
    k_count<<<(E + 255) / 256, 256, 0, sB>>>(ei, E);
    k_blocksum<<<512, 1024, 0, sB>>>();
    k_scan_bsums<<<1, 512, 0, sB>>>();
    k_scan_final<<<512, 1024, 0, sB>>>();
    k_fill<<<(E + NN + 255) / 256, 256, 0, sB>>>(ei, E);
    k_node_linear<14, 14, 14, 16><<<(NN + 255) / 256, 256, 0, sB>>>(x, W1, as1, ad1, hbuf, sv, tv);
    k_gat_agg<14, 16, 16><<<(NN * 32 + 255) / 256, 256, 0, sB>>>(hbuf, sv, tv, b1, gbuf);
    k_node_linear<14, 16, 32, 32><<<(NN + 255) / 256, 256, 0, sB>>>(gbuf, W2, as2, ad2, hbuf, sv, tv);
    k_gat_agg<32, 32, 32><<<(NN * 32 + 255) / 256, 256, 0, sB>>>(hbuf, sv, tv, b2, gbuf);
    k_pool<<<(BB * 32 + 255) / 256, 256, 0, sB>>>(batch, gbuf, hf + O_CMB);

    // ---- dense branch continues (stream 0) ----
    k_prep<<<2, 256>>>(fc3_b, bn3, 400, scl + 600, shf + 600);
    // fc3: [16384,256]x[256,400] -> tv1
    k_mma<<<dim3(7, 128), 256, SM_TOTAL>>>(hf + O_ATV, hf + O_W3_H, hf + O_W3_L,
                                           256, scl + 600, shf + 600,
                                           nullptr, hf + O_TV1, 448, 0, 400, 448);
    k_whalf<<<(256 * 448 + 255) / 256, 256>>>(fc2_w, 400, 200, 448, 256, hf + O_W2_H, hf + O_W2_L);
    k_prep<<<1, 256>>>(fc2_b, bn2, 200, scl + 400, shf + 400);
    // fc2: [16384,448]x[448,200] -> comb[:,32:232]
    k_mma<<<dim3(4, 128), 256, SM_TOTAL>>>(hf + O_FP1, hf + O_W2_H, hf + O_W2_L,
                                           448, scl + 400, shf + 400,
                                           nullptr, hf + O_CMB, 448, 32, 200, 200);
    k_whalf<<<(256 * 448 + 255) / 256, 256>>>(fc4_w, 400, 200, 448, 256, hf + O_W4_H, hf + O_W4_L);
    k_prep<<<1, 256>>>(fc4_b, bn4, 200, scl + 1000, shf + 1000);
    // fc4: [16384,448]x[448,200] -> comb[:,232:432], zero comb[:,432:448]
    k_mma<<<dim3(4, 128), 256, SM_TOTAL>>>(hf + O_TV1, hf + O_W4_H, hf + O_W4_L,
                                           448, scl + 1000, shf + 1000,
                                           nullptr, hf + O_CMB, 448, 232, 200, 216);
    k_whalf<<<(128 * 448 + 255) / 256, 256>>>(fcc1_w, 432, 100, 448, 128, hf + O_WC_H, hf + O_WC_L);
    k_prep<<<1, 128>>>(fcc1_b, bnc, 100, scl + 1200, shf + 1200);

    // join: fcc1 needs comb (pool on sB + fc2/fc4 on 0)
    cudaEventRecord(evJ, sB);
    cudaStreamWaitEvent(0, evJ, 0);

    // fcc1: [16384,448]x[448,100] -> c1 fp32
    k_mma<<<dim3(2, 128), 256, SM_TOTAL>>>(hf + O_CMB, hf + O_WC_H, hf + O_WC_L,
                                           448, scl + 1200, shf + 1200,
                                           c1, nullptr, 100, 0, 100, 100);
    k_final<<<(BB + 127) / 128, 128>>>(c1, fcc2_w, fcc2_b, out);
}